// round 1
// baseline (speedup 1.0000x reference)
#include <cuda_runtime.h>
#include <math.h>

#define D_MODEL 1024
#define NHEADS  16
#define DKH     64
#define D_FF    4096
#define BATCH   2
#define SEQ     2048
#define NROWS   (BATCH*SEQ)
#define LN_EPS  1e-6f

// ---------------- scratch (device globals: allocation-free) ----------------
__device__ float g_Q  [(size_t)NROWS*D_MODEL];
__device__ float g_K  [(size_t)NROWS*D_MODEL];
__device__ float g_V  [(size_t)NROWS*D_MODEL];
__device__ float g_ctx[(size_t)NROWS*D_MODEL];
__device__ float g_t1 [(size_t)NROWS*D_MODEL];
__device__ float g_h  [(size_t)NROWS*D_MODEL];
__device__ float g_f1 [(size_t)NROWS*D_FF];

// ---------------- GEMM: C[N,M] = A[N,K] @ W[K,M] + bias (opt ReLU) ----------
// 128x128 block tile, K-tile 16, 256 threads, 8x8 per thread (2x2 quadrants of 4x4)
template<bool RELU>
__global__ __launch_bounds__(256)
void gemm_bias_kernel(const float* __restrict__ A, const float* __restrict__ W,
                      const float* __restrict__ bias, float* __restrict__ C,
                      int N, int K, int M)
{
    __shared__ float As[16*132];   // transposed A tile, padded pitch 132
    __shared__ float Bs[16*128];
    const int tid  = threadIdx.x;
    const int tr   = tid >> 4;     // 0..15
    const int tc   = tid & 15;     // 0..15
    const int brow = blockIdx.y * 128;
    const int bcol = blockIdx.x * 128;

    float acc[2][2][4][4];
    #pragma unroll
    for (int a=0;a<2;a++)
      #pragma unroll
      for (int b=0;b<2;b++)
        #pragma unroll
        for (int i=0;i<4;i++)
          #pragma unroll
          for (int j=0;j<4;j++) acc[a][b][i][j]=0.f;

    const int nkt = K >> 4;
    for (int kt = 0; kt < nkt; kt++) {
        // load A tile 128x16 (coalesced), store transposed As[k][m]
        #pragma unroll
        for (int t = 0; t < 2; t++) {
            int f   = tid + t*256;       // 0..511
            int row = f >> 2;            // 0..127
            int c4  = f & 3;             // 0..3
            float4 av = *(const float4*)(A + (size_t)(brow+row)*K + (kt<<4) + (c4<<2));
            As[(c4*4+0)*132 + row] = av.x;
            As[(c4*4+1)*132 + row] = av.y;
            As[(c4*4+2)*132 + row] = av.z;
            As[(c4*4+3)*132 + row] = av.w;
        }
        // load W tile 16x128 (coalesced)
        #pragma unroll
        for (int t = 0; t < 2; t++) {
            int f   = tid + t*256;
            int row = f >> 5;            // 0..15
            int c4  = f & 31;            // 0..31
            *(float4*)(Bs + row*128 + (c4<<2)) =
                *(const float4*)(W + (size_t)((kt<<4)+row)*M + bcol + (c4<<2));
        }
        __syncthreads();
        #pragma unroll
        for (int k = 0; k < 16; k++) {
            float4 a0 = *(const float4*)(As + k*132 +      tr*4);
            float4 a1 = *(const float4*)(As + k*132 + 64 + tr*4);
            float4 b0 = *(const float4*)(Bs + k*128 +      tc*4);
            float4 b1 = *(const float4*)(Bs + k*128 + 64 + tc*4);
            float ar[2][4] = {{a0.x,a0.y,a0.z,a0.w},{a1.x,a1.y,a1.z,a1.w}};
            float br[2][4] = {{b0.x,b0.y,b0.z,b0.w},{b1.x,b1.y,b1.z,b1.w}};
            #pragma unroll
            for (int qi=0;qi<2;qi++)
              #pragma unroll
              for (int i=0;i<4;i++)
                #pragma unroll
                for (int qj=0;qj<2;qj++)
                  #pragma unroll
                  for (int j=0;j<4;j++)
                    acc[qi][qj][i][j] += ar[qi][i]*br[qj][j];
        }
        __syncthreads();
    }
    // epilogue
    #pragma unroll
    for (int qi=0;qi<2;qi++)
      #pragma unroll
      for (int i=0;i<4;i++) {
        int row = brow + qi*64 + tr*4 + i;
        #pragma unroll
        for (int qj=0;qj<2;qj++) {
          int col = bcol + qj*64 + tc*4;
          float4 bv = *(const float4*)(bias + col);
          float4 o;
          o.x = acc[qi][qj][i][0] + bv.x;
          o.y = acc[qi][qj][i][1] + bv.y;
          o.z = acc[qi][qj][i][2] + bv.z;
          o.w = acc[qi][qj][i][3] + bv.w;
          if (RELU) {
            o.x=fmaxf(o.x,0.f); o.y=fmaxf(o.y,0.f);
            o.z=fmaxf(o.z,0.f); o.w=fmaxf(o.w,0.f);
          }
          *(float4*)(C + (size_t)row*M + col) = o;
        }
      }
}

// ---------------- flash attention (fp32, online softmax) -------------------
// grid: (SEQ/64, BATCH*NHEADS). 256 threads. BQ=BK=64, dk=64.
#define ATT_SMEM_FLOATS (64*64 + 64*65 + 64*65 + 64*64 + 3*64)
#define ATT_SMEM_BYTES  (ATT_SMEM_FLOATS*4)

__global__ __launch_bounds__(256)
void attention_kernel(const float* __restrict__ Q, const float* __restrict__ K,
                      const float* __restrict__ V, float* __restrict__ ctx)
{
    extern __shared__ float sm[];
    float* Qs  = sm;              // [64][64]  (broadcast access -> no pad needed)
    float* Ks  = Qs + 64*64;      // [64][65]
    float* Ss  = Ks + 64*65;      // [64][65]
    float* Vs  = Ss + 64*65;      // [64][64]
    float* m_s = Vs + 64*64;      // [64]
    float* l_s = m_s + 64;        // [64]
    float* a_s = l_s + 64;        // [64]

    const int tid = threadIdx.x;
    const int bh  = blockIdx.y;
    const int b   = bh >> 4;           // NHEADS = 16
    const int hh  = bh & 15;
    const int q0  = blockIdx.x * 64;
    const size_t base = (size_t)b*SEQ*D_MODEL + (size_t)hh*DKH;

    for (int i=tid; i<64*64; i+=256) {
        int r=i>>6, c=i&63;
        Qs[r*64+c] = Q[base + (size_t)(q0+r)*D_MODEL + c] * 0.125f;  // 1/sqrt(64)
    }
    if (tid < 64) { m_s[tid] = -1e30f; l_s[tid] = 0.f; }
    const int ty = tid>>4, tx = tid&15;
    const int r0 = ty*4, c0 = tx*4;
    float O[4][4];
    #pragma unroll
    for (int i=0;i<4;i++)
      #pragma unroll
      for (int j=0;j<4;j++) O[i][j]=0.f;
    __syncthreads();

    for (int kt = 0; kt < SEQ/64; kt++) {
        const int k0 = kt*64;
        for (int i=tid; i<64*64; i+=256) {
            int r=i>>6, c=i&63;
            Ks[r*65+c] = K[base + (size_t)(k0+r)*D_MODEL + c];
        }
        __syncthreads();
        // S = Q * K^T (prescaled)
        float s[4][4];
        #pragma unroll
        for (int i=0;i<4;i++)
          #pragma unroll
          for (int j=0;j<4;j++) s[i][j]=0.f;
        #pragma unroll 8
        for (int k=0;k<64;k++){
            float qv[4], kv[4];
            #pragma unroll
            for (int i=0;i<4;i++) qv[i]=Qs[(r0+i)*64+k];
            #pragma unroll
            for (int j=0;j<4;j++) kv[j]=Ks[(c0+j)*65+k];
            #pragma unroll
            for (int i=0;i<4;i++)
              #pragma unroll
              for (int j=0;j<4;j++)
                s[i][j] += qv[i]*kv[j];
        }
        #pragma unroll
        for (int i=0;i<4;i++)
          #pragma unroll
          for (int j=0;j<4;j++)
            Ss[(r0+i)*65 + c0+j] = s[i][j];
        __syncthreads();
        // load V tile (all threads), then rowwise online softmax (first 64 threads)
        for (int i=tid; i<64*64; i+=256) {
            int r=i>>6, c=i&63;
            Vs[r*64+c] = V[base + (size_t)(k0+r)*D_MODEL + c];
        }
        if (tid < 64) {
            float  mo   = m_s[tid];
            float* srow = Ss + tid*65;
            float  mx   = mo;
            #pragma unroll 16
            for (int c=0;c<64;c++) mx = fmaxf(mx, srow[c]);
            float al  = __expf(mo - mx);
            float sum = 0.f;
            #pragma unroll 16
            for (int c=0;c<64;c++){ float p = __expf(srow[c]-mx); srow[c]=p; sum+=p; }
            l_s[tid] = l_s[tid]*al + sum;
            m_s[tid] = mx;
            a_s[tid] = al;
        }
        __syncthreads();
        float al[4];
        #pragma unroll
        for (int i=0;i<4;i++) al[i]=a_s[r0+i];
        #pragma unroll
        for (int i=0;i<4;i++)
          #pragma unroll
          for (int j=0;j<4;j++) O[i][j] *= al[i];
        #pragma unroll 8
        for (int k=0;k<64;k++){
            float pv[4], vv[4];
            #pragma unroll
            for (int i=0;i<4;i++) pv[i]=Ss[(r0+i)*65+k];
            #pragma unroll
            for (int j=0;j<4;j++) vv[j]=Vs[k*64 + c0+j];
            #pragma unroll
            for (int i=0;i<4;i++)
              #pragma unroll
              for (int j=0;j<4;j++)
                O[i][j] += pv[i]*vv[j];
        }
        __syncthreads();
    }
    float li[4];
    #pragma unroll
    for (int i=0;i<4;i++) li[i] = 1.f / l_s[r0+i];
    #pragma unroll
    for (int i=0;i<4;i++){
        size_t o = base + (size_t)(q0+r0+i)*D_MODEL + c0;
        #pragma unroll
        for (int j=0;j<4;j++) ctx[o+j] = O[i][j]*li[i];
    }
}

// ---------------- fused residual add + LayerNorm ---------------------------
// out = gamma * (v - mean)/(sqrt(mean((v-mean)^2)) + eps) + beta, v = A+Bm
__global__ __launch_bounds__(256)
void add_ln_kernel(const float* __restrict__ A, const float* __restrict__ Bm,
                   const float* __restrict__ gamma, const float* __restrict__ beta,
                   float* __restrict__ out)
{
    __shared__ float sh[8];
    const int row = blockIdx.x;
    const int tid = threadIdx.x;
    const float* a  = A  + (size_t)row*D_MODEL;
    const float* bb = Bm + (size_t)row*D_MODEL;
    float v[4];
    float s = 0.f;
    #pragma unroll
    for (int i=0;i<4;i++){ int c = tid + i*256; v[i]=a[c]+bb[c]; s+=v[i]; }
    #pragma unroll
    for (int o=16;o;o>>=1) s += __shfl_xor_sync(0xffffffffu, s, o);
    if ((tid&31)==0) sh[tid>>5] = s;
    __syncthreads();
    float tot = 0.f;
    #pragma unroll
    for (int i=0;i<8;i++) tot += sh[i];
    const float mean = tot * (1.f/(float)D_MODEL);
    float s2 = 0.f;
    #pragma unroll
    for (int i=0;i<4;i++){ float d=v[i]-mean; s2 += d*d; }
    #pragma unroll
    for (int o=16;o;o>>=1) s2 += __shfl_xor_sync(0xffffffffu, s2, o);
    __syncthreads();
    if ((tid&31)==0) sh[tid>>5] = s2;
    __syncthreads();
    float tot2 = 0.f;
    #pragma unroll
    for (int i=0;i<8;i++) tot2 += sh[i];
    const float inv = 1.f / (sqrtf(tot2 * (1.f/(float)D_MODEL)) + LN_EPS);
    #pragma unroll
    for (int i=0;i<4;i++){
        int c = tid + i*256;
        out[(size_t)row*D_MODEL + c] = gamma[c]*(v[i]-mean)*inv + beta[c];
    }
}

// ---------------- launcher --------------------------------------------------
extern "C" void kernel_launch(void* const* d_in, const int* in_sizes, int n_in,
                              void* d_out, int out_size)
{
    const float* x   = (const float*)d_in[0];
    const float* Wq  = (const float*)d_in[1];
    const float* bq  = (const float*)d_in[2];
    const float* Wk  = (const float*)d_in[3];
    const float* bk  = (const float*)d_in[4];
    const float* Wv  = (const float*)d_in[5];
    const float* bv  = (const float*)d_in[6];
    const float* Wo  = (const float*)d_in[7];
    const float* bo  = (const float*)d_in[8];
    const float* W1  = (const float*)d_in[9];
    const float* b1  = (const float*)d_in[10];
    const float* W2  = (const float*)d_in[11];
    const float* b2  = (const float*)d_in[12];
    const float* g1  = (const float*)d_in[13];
    const float* be1 = (const float*)d_in[14];
    const float* g2  = (const float*)d_in[15];
    const float* be2 = (const float*)d_in[16];
    float* out = (float*)d_out;

    float *Q,*Kb,*V,*ctx,*t1,*h,*f1;
    cudaGetSymbolAddress((void**)&Q,   g_Q);
    cudaGetSymbolAddress((void**)&Kb,  g_K);
    cudaGetSymbolAddress((void**)&V,   g_V);
    cudaGetSymbolAddress((void**)&ctx, g_ctx);
    cudaGetSymbolAddress((void**)&t1,  g_t1);
    cudaGetSymbolAddress((void**)&h,   g_h);
    cudaGetSymbolAddress((void**)&f1,  g_f1);

    dim3 thr(256);
    dim3 gD(D_MODEL/128, NROWS/128);   // (8, 32)
    dim3 gF(D_FF/128,    NROWS/128);   // (32, 32)

    // QKV projections
    gemm_bias_kernel<false><<<gD, thr>>>(x, Wq, bq, Q,  NROWS, D_MODEL, D_MODEL);
    gemm_bias_kernel<false><<<gD, thr>>>(x, Wk, bk, Kb, NROWS, D_MODEL, D_MODEL);
    gemm_bias_kernel<false><<<gD, thr>>>(x, Wv, bv, V,  NROWS, D_MODEL, D_MODEL);

    // attention
    cudaFuncSetAttribute(attention_kernel,
                         cudaFuncAttributeMaxDynamicSharedMemorySize, ATT_SMEM_BYTES);
    attention_kernel<<<dim3(SEQ/64, BATCH*NHEADS), thr, ATT_SMEM_BYTES>>>(Q, Kb, V, ctx);

    // output projection + LN1
    gemm_bias_kernel<false><<<gD, thr>>>(ctx, Wo, bo, t1, NROWS, D_MODEL, D_MODEL);
    add_ln_kernel<<<NROWS, thr>>>(x, t1, g1, be1, h);

    // FFN + LN2
    gemm_bias_kernel<true ><<<gF, thr>>>(h,  W1, b1, f1, NROWS, D_MODEL, D_FF);
    gemm_bias_kernel<false><<<gD, thr>>>(f1, W2, b2, t1, NROWS, D_FF, D_MODEL);
    add_ln_kernel<<<NROWS, thr>>>(h, t1, g2, be2, out);
}

// round 3
// speedup vs baseline: 1.5601x; 1.5601x over previous
#include <cuda_runtime.h>
#include <cuda_bf16.h>
#include <math.h>
#include <stdint.h>

#define D_MODEL 1024
#define NHEADS  16
#define DKH     64
#define D_FF    4096
#define BATCH   2
#define SEQ     2048
#define NROWS   (BATCH*SEQ)
#define LN_EPS  1e-6f

#define SWZ128(x) ((x) ^ (((x) >> 3) & 0x70))

// ================= warp MMA helpers (sm_80+ HMMA, legal on sm_100) ========
__device__ __forceinline__ uint32_t smem_u32(const void* p) {
    uint32_t a;
    asm("{ .reg .u64 t; cvta.to.shared.u64 t, %1; cvt.u32.u64 %0, t; }" : "=r"(a) : "l"(p));
    return a;
}
__device__ __forceinline__ void ldsm_x4(uint32_t& r0, uint32_t& r1, uint32_t& r2, uint32_t& r3, uint32_t addr) {
    asm volatile("ldmatrix.sync.aligned.m8n8.x4.shared.b16 {%0,%1,%2,%3}, [%4];"
                 : "=r"(r0), "=r"(r1), "=r"(r2), "=r"(r3) : "r"(addr));
}
__device__ __forceinline__ void mma_bf16(float* c, uint32_t a0, uint32_t a1, uint32_t a2, uint32_t a3,
                                         uint32_t b0, uint32_t b1) {
    asm volatile(
        "mma.sync.aligned.m16n8k16.row.col.f32.bf16.bf16.f32 "
        "{%0,%1,%2,%3}, {%4,%5,%6,%7}, {%8,%9}, {%0,%1,%2,%3};"
        : "+f"(c[0]), "+f"(c[1]), "+f"(c[2]), "+f"(c[3])
        : "r"(a0), "r"(a1), "r"(a2), "r"(a3), "r"(b0), "r"(b1));
}
__device__ __forceinline__ void cp16(uint32_t saddr, const void* gptr) {
    asm volatile("cp.async.cg.shared.global [%0], [%1], 16;" :: "r"(saddr), "l"(gptr));
}
#define CP_COMMIT() asm volatile("cp.async.commit_group;" ::: "memory")
#define CP_WAIT(n)  asm volatile("cp.async.wait_group %0;" :: "n"(n) : "memory")

// ================= scratch =================
__device__ float g_Q [(size_t)NROWS*D_MODEL];
__device__ float g_K [(size_t)NROWS*D_MODEL];
__device__ float g_V [(size_t)NROWS*D_MODEL];
__device__ float g_t1[(size_t)NROWS*D_MODEL];
__device__ float g_h [(size_t)NROWS*D_MODEL];

__device__ __nv_bfloat16 g_xh [(size_t)NROWS*D_MODEL], g_xl [(size_t)NROWS*D_MODEL];
__device__ __nv_bfloat16 g_ch [(size_t)NROWS*D_MODEL], g_cl [(size_t)NROWS*D_MODEL];
__device__ __nv_bfloat16 g_hh [(size_t)NROWS*D_MODEL], g_hl [(size_t)NROWS*D_MODEL];
__device__ __nv_bfloat16 g_f1h[(size_t)NROWS*D_FF],    g_f1l[(size_t)NROWS*D_FF];
__device__ __nv_bfloat16 g_wqh[(size_t)D_MODEL*D_MODEL], g_wql[(size_t)D_MODEL*D_MODEL];
__device__ __nv_bfloat16 g_wkh[(size_t)D_MODEL*D_MODEL], g_wkl[(size_t)D_MODEL*D_MODEL];
__device__ __nv_bfloat16 g_wvh[(size_t)D_MODEL*D_MODEL], g_wvl[(size_t)D_MODEL*D_MODEL];
__device__ __nv_bfloat16 g_woh[(size_t)D_MODEL*D_MODEL], g_wol[(size_t)D_MODEL*D_MODEL];
__device__ __nv_bfloat16 g_w1h[(size_t)D_FF*D_MODEL],    g_w1l[(size_t)D_FF*D_MODEL];  // W1^T
__device__ __nv_bfloat16 g_w2h[(size_t)D_MODEL*D_FF],    g_w2l[(size_t)D_MODEL*D_FF];  // W2^T

// ================= conversion kernels =================
__global__ __launch_bounds__(256)
void split_f32_kernel(const float* __restrict__ in, __nv_bfloat16* __restrict__ hi,
                      __nv_bfloat16* __restrict__ lo, int n)
{
    int i = (blockIdx.x * 256 + threadIdx.x) * 4;
    if (i >= n) return;
    float4 v = *(const float4*)(in + i);
    float vv[4] = {v.x, v.y, v.z, v.w};
    #pragma unroll
    for (int j = 0; j < 4; j++) {
        __nv_bfloat16 h = __float2bfloat16(vv[j]);
        hi[i+j] = h;
        lo[i+j] = __float2bfloat16(vv[j] - __bfloat162float(h));
    }
}

// W [K, M] f32 -> Wt_hi/Wt_lo [M, K] bf16
__global__ __launch_bounds__(256)
void transpose_split_kernel(const float* __restrict__ W, __nv_bfloat16* __restrict__ Th,
                            __nv_bfloat16* __restrict__ Tl, int K, int M)
{
    __shared__ float ts[32][33];
    const int m0 = blockIdx.x * 32, k0 = blockIdx.y * 32;
    const int tx = threadIdx.x, ty = threadIdx.y;   // 32 x 8
    #pragma unroll
    for (int i = 0; i < 4; i++) {
        int k = ty + i*8;
        ts[k][tx] = W[(size_t)(k0+k)*M + m0 + tx];
    }
    __syncthreads();
    #pragma unroll
    for (int i = 0; i < 4; i++) {
        int m = ty + i*8;
        float v = ts[tx][m];
        __nv_bfloat16 h = __float2bfloat16(v);
        size_t o = (size_t)(m0+m)*K + k0 + tx;
        Th[o] = h;
        Tl[o] = __float2bfloat16(v - __bfloat162float(h));
    }
}

// ================= mma.sync split-bf16 GEMM ================================
// C[row,col] = sum_k (Ah+Al)[row,k] * (Bh+Bl)[col,k] + bias[col]
// Terms: hi*hi + hi*lo + lo*hi (lo*lo negligible).
// MODE 0: f32 out. MODE 1: relu + split-bf16 out.
// Smem: 2 buffers x (Ah|Al|Bh|Bl, 16KB each) = 128KB, SW128-swizzled 128B rows.
#define GEMM_SMEM (2*65536)

template<int MODE>
__global__ __launch_bounds__(256)
void gemm_mma(const __nv_bfloat16* __restrict__ Ah, const __nv_bfloat16* __restrict__ Al,
              const __nv_bfloat16* __restrict__ Bh, const __nv_bfloat16* __restrict__ Bl,
              const float* __restrict__ bias,
              float* __restrict__ Cf, __nv_bfloat16* __restrict__ Ch, __nv_bfloat16* __restrict__ Cl,
              int K, int M)
{
    extern __shared__ char sb[];
    const int tid  = threadIdx.x;
    const int wid  = tid >> 5;
    const int lane = tid & 31;
    const int wm   = wid >> 2;            // 0..1
    const int wn   = wid & 3;             // 0..3
    const int brow = blockIdx.y * 128;
    const int bcol = blockIdx.x * 128;
    const uint32_t sbu = smem_u32(sb);

    float acc[4][4][4];
    #pragma unroll
    for (int mf = 0; mf < 4; mf++)
      #pragma unroll
      for (int nf = 0; nf < 4; nf++)
        #pragma unroll
        for (int q = 0; q < 4; q++) acc[mf][nf][q] = 0.f;

    const int NC = K >> 6;   // 64-elem chunks

    // prefetch helper pattern: 16 cp.async of 16B per thread per chunk
    const __nv_bfloat16* srcs[4] = {Ah, Al, Bh, Bl};
    const int bases[4] = {brow, brow, bcol, bcol};

    // --- prefetch chunk 0 ---
    {
        const int kc = 0;
        #pragma unroll
        for (int it = 0; it < 16; it++) {
            int idx  = tid + it*256;           // 0..4095
            int tile = idx >> 10;              // 0..3
            int rem  = idx & 1023;
            int r    = rem >> 3;               // 0..127
            int chn  = rem & 7;                // 0..7
            const __nv_bfloat16* g = srcs[tile] + (size_t)(bases[tile] + r)*K + kc + chn*8;
            uint32_t so = (uint32_t)tile*16384u + SWZ128((uint32_t)((r << 7) + (chn << 4)));
            cp16(sbu + so, g);
        }
        CP_COMMIT();
    }

    for (int c = 0; c < NC; c++) {
        if (c + 1 < NC) {
            const int kc = (c+1) << 6;
            const uint32_t boff = (uint32_t)((c+1) & 1) * 65536u;
            #pragma unroll
            for (int it = 0; it < 16; it++) {
                int idx  = tid + it*256;
                int tile = idx >> 10;
                int rem  = idx & 1023;
                int r    = rem >> 3;
                int chn  = rem & 7;
                const __nv_bfloat16* g = srcs[tile] + (size_t)(bases[tile] + r)*K + kc + chn*8;
                uint32_t so = boff + (uint32_t)tile*16384u + SWZ128((uint32_t)((r << 7) + (chn << 4)));
                cp16(sbu + so, g);
            }
            CP_COMMIT();
            CP_WAIT(1);
        } else {
            CP_WAIT(0);
        }
        __syncthreads();

        const uint32_t buf = sbu + (uint32_t)(c & 1) * 65536u;
        const uint32_t aHb = buf;
        const uint32_t aLb = buf + 16384u;
        const uint32_t bHb = buf + 32768u;
        const uint32_t bLb = buf + 49152u;

        // per-lane ldmatrix row/col pieces
        const int rloc   = (lane & 7) + ((lane >> 3) & 1) * 8;  // 0..15
        const int kpiece = (lane >> 4) << 4;                    // 0 or 16 bytes

        #pragma unroll
        for (int ks = 0; ks < 4; ks++) {
            const uint32_t wb = (uint32_t)(ks*32 + kpiece);
            uint32_t ah[4][4], al[4][4];
            #pragma unroll
            for (int mf = 0; mf < 4; mf++) {
                uint32_t off = SWZ128((uint32_t)(((wm*64 + mf*16 + rloc) << 7)) + wb);
                ldsm_x4(ah[mf][0], ah[mf][1], ah[mf][2], ah[mf][3], aHb + off);
                ldsm_x4(al[mf][0], al[mf][1], al[mf][2], al[mf][3], aLb + off);
            }
            uint32_t bh[2][4], bl[2][4];
            #pragma unroll
            for (int g = 0; g < 2; g++) {
                uint32_t off = SWZ128((uint32_t)(((wn*32 + g*16 + rloc) << 7)) + wb);
                ldsm_x4(bh[g][0], bh[g][1], bh[g][2], bh[g][3], bHb + off);
                ldsm_x4(bl[g][0], bl[g][1], bl[g][2], bl[g][3], bLb + off);
            }
            #pragma unroll
            for (int mf = 0; mf < 4; mf++) {
                #pragma unroll
                for (int g = 0; g < 2; g++) {
                    #pragma unroll
                    for (int s = 0; s < 2; s++) {
                        const int nf = g*2 + s;
                        uint32_t bh0 = s ? bh[g][1] : bh[g][0];
                        uint32_t bh1 = s ? bh[g][3] : bh[g][2];
                        uint32_t bl0 = s ? bl[g][1] : bl[g][0];
                        uint32_t bl1 = s ? bl[g][3] : bl[g][2];
                        mma_bf16(acc[mf][nf], ah[mf][0], ah[mf][1], ah[mf][2], ah[mf][3], bh0, bh1);
                        mma_bf16(acc[mf][nf], ah[mf][0], ah[mf][1], ah[mf][2], ah[mf][3], bl0, bl1);
                        mma_bf16(acc[mf][nf], al[mf][0], al[mf][1], al[mf][2], al[mf][3], bh0, bh1);
                    }
                }
            }
        }
        __syncthreads();
    }

    // ---- epilogue ----
    const int qr = lane >> 2;          // 0..7
    const int qc = (lane & 3) * 2;     // 0,2,4,6
    #pragma unroll
    for (int mf = 0; mf < 4; mf++) {
        #pragma unroll
        for (int nf = 0; nf < 4; nf++) {
            const int row = brow + wm*64 + mf*16 + qr;
            const int col = bcol + wn*32 + nf*8 + qc;
            const float b0 = __ldg(bias + col), b1 = __ldg(bias + col + 1);
            float v00 = acc[mf][nf][0] + b0, v01 = acc[mf][nf][1] + b1;
            float v10 = acc[mf][nf][2] + b0, v11 = acc[mf][nf][3] + b1;
            if (MODE == 0) {
                *(float2*)(Cf + (size_t)row*M + col)     = make_float2(v00, v01);
                *(float2*)(Cf + (size_t)(row+8)*M + col) = make_float2(v10, v11);
            } else {
                v00 = fmaxf(v00, 0.f); v01 = fmaxf(v01, 0.f);
                v10 = fmaxf(v10, 0.f); v11 = fmaxf(v11, 0.f);
                __nv_bfloat16 h00 = __float2bfloat16(v00), h01 = __float2bfloat16(v01);
                __nv_bfloat16 h10 = __float2bfloat16(v10), h11 = __float2bfloat16(v11);
                uint32_t hp0 = (uint32_t)__bfloat16_as_ushort(h00) | ((uint32_t)__bfloat16_as_ushort(h01) << 16);
                uint32_t hp1 = (uint32_t)__bfloat16_as_ushort(h10) | ((uint32_t)__bfloat16_as_ushort(h11) << 16);
                __nv_bfloat16 l00 = __float2bfloat16(v00 - __bfloat162float(h00));
                __nv_bfloat16 l01 = __float2bfloat16(v01 - __bfloat162float(h01));
                __nv_bfloat16 l10 = __float2bfloat16(v10 - __bfloat162float(h10));
                __nv_bfloat16 l11 = __float2bfloat16(v11 - __bfloat162float(h11));
                uint32_t lp0 = (uint32_t)__bfloat16_as_ushort(l00) | ((uint32_t)__bfloat16_as_ushort(l01) << 16);
                uint32_t lp1 = (uint32_t)__bfloat16_as_ushort(l10) | ((uint32_t)__bfloat16_as_ushort(l11) << 16);
                *(uint32_t*)(Ch + (size_t)row*M + col)     = hp0;
                *(uint32_t*)(Ch + (size_t)(row+8)*M + col) = hp1;
                *(uint32_t*)(Cl + (size_t)row*M + col)     = lp0;
                *(uint32_t*)(Cl + (size_t)(row+8)*M + col) = lp1;
            }
        }
    }
}

// ================= flash attention (fp32 SIMT), split-bf16 output ==========
#define ATT_SMEM_FLOATS (64*64 + 64*65 + 64*65 + 64*64 + 3*64)
#define ATT_SMEM_BYTES  (ATT_SMEM_FLOATS*4)

__global__ __launch_bounds__(256)
void attention_kernel(const float* __restrict__ Q, const float* __restrict__ K,
                      const float* __restrict__ V,
                      __nv_bfloat16* __restrict__ ctxh, __nv_bfloat16* __restrict__ ctxl)
{
    extern __shared__ float sm[];
    float* Qs  = sm;
    float* Ks  = Qs + 64*64;
    float* Ss  = Ks + 64*65;
    float* Vs  = Ss + 64*65;
    float* m_s = Vs + 64*64;
    float* l_s = m_s + 64;
    float* a_s = l_s + 64;

    const int tid = threadIdx.x;
    const int bh  = blockIdx.y;
    const int b   = bh >> 4;
    const int hh  = bh & 15;
    const int q0  = blockIdx.x * 64;
    const size_t base = (size_t)b*SEQ*D_MODEL + (size_t)hh*DKH;

    for (int i = tid; i < 64*64; i += 256) {
        int r = i >> 6, c = i & 63;
        Qs[r*64+c] = Q[base + (size_t)(q0+r)*D_MODEL + c] * 0.125f;
    }
    if (tid < 64) { m_s[tid] = -1e30f; l_s[tid] = 0.f; }
    const int ty = tid >> 4, tx = tid & 15;
    const int r0 = ty*4, c0 = tx*4;
    float O[4][4];
    #pragma unroll
    for (int i = 0; i < 4; i++)
      #pragma unroll
      for (int jj = 0; jj < 4; jj++) O[i][jj] = 0.f;
    __syncthreads();

    for (int kt = 0; kt < SEQ/64; kt++) {
        const int k0 = kt*64;
        for (int i = tid; i < 64*64; i += 256) {
            int r = i >> 6, c = i & 63;
            Ks[r*65+c] = K[base + (size_t)(k0+r)*D_MODEL + c];
        }
        __syncthreads();
        float s[4][4];
        #pragma unroll
        for (int i = 0; i < 4; i++)
          #pragma unroll
          for (int jj = 0; jj < 4; jj++) s[i][jj] = 0.f;
        #pragma unroll 8
        for (int k = 0; k < 64; k++) {
            float qv[4], kv[4];
            #pragma unroll
            for (int i = 0; i < 4; i++) qv[i] = Qs[(r0+i)*64+k];
            #pragma unroll
            for (int jj = 0; jj < 4; jj++) kv[jj] = Ks[(c0+jj)*65+k];
            #pragma unroll
            for (int i = 0; i < 4; i++)
              #pragma unroll
              for (int jj = 0; jj < 4; jj++)
                s[i][jj] += qv[i]*kv[jj];
        }
        #pragma unroll
        for (int i = 0; i < 4; i++)
          #pragma unroll
          for (int jj = 0; jj < 4; jj++)
            Ss[(r0+i)*65 + c0+jj] = s[i][jj];
        __syncthreads();
        for (int i = tid; i < 64*64; i += 256) {
            int r = i >> 6, c = i & 63;
            Vs[r*64+c] = V[base + (size_t)(k0+r)*D_MODEL + c];
        }
        if (tid < 64) {
            float  mo   = m_s[tid];
            float* srow = Ss + tid*65;
            float  mx   = mo;
            #pragma unroll 16
            for (int c = 0; c < 64; c++) mx = fmaxf(mx, srow[c]);
            float al  = __expf(mo - mx);
            float sum = 0.f;
            #pragma unroll 16
            for (int c = 0; c < 64; c++) { float p = __expf(srow[c]-mx); srow[c] = p; sum += p; }
            l_s[tid] = l_s[tid]*al + sum;
            m_s[tid] = mx;
            a_s[tid] = al;
        }
        __syncthreads();
        float al[4];
        #pragma unroll
        for (int i = 0; i < 4; i++) al[i] = a_s[r0+i];
        #pragma unroll
        for (int i = 0; i < 4; i++)
          #pragma unroll
          for (int jj = 0; jj < 4; jj++) O[i][jj] *= al[i];
        #pragma unroll 8
        for (int k = 0; k < 64; k++) {
            float pv[4], vv[4];
            #pragma unroll
            for (int i = 0; i < 4; i++) pv[i] = Ss[(r0+i)*65+k];
            #pragma unroll
            for (int jj = 0; jj < 4; jj++) vv[jj] = Vs[k*64 + c0+jj];
            #pragma unroll
            for (int i = 0; i < 4; i++)
              #pragma unroll
              for (int jj = 0; jj < 4; jj++)
                O[i][jj] += pv[i]*vv[jj];
        }
        __syncthreads();
    }
    float li[4];
    #pragma unroll
    for (int i = 0; i < 4; i++) li[i] = 1.f / l_s[r0+i];
    #pragma unroll
    for (int i = 0; i < 4; i++) {
        size_t o = base + (size_t)(q0+r0+i)*D_MODEL + c0;
        #pragma unroll
        for (int jj = 0; jj < 4; jj++) {
            float v = O[i][jj]*li[i];
            __nv_bfloat16 h = __float2bfloat16(v);
            ctxh[o+jj] = h;
            ctxl[o+jj] = __float2bfloat16(v - __bfloat162float(h));
        }
    }
}

// ================= residual add + LayerNorm (opt split-bf16 copy) ==========
template<bool SPLIT>
__global__ __launch_bounds__(256)
void add_ln_kernel(const float* __restrict__ A, const float* __restrict__ Bm,
                   const float* __restrict__ gamma, const float* __restrict__ beta,
                   float* __restrict__ out, __nv_bfloat16* __restrict__ oh,
                   __nv_bfloat16* __restrict__ ol)
{
    __shared__ float sh[8];
    const int row = blockIdx.x;
    const int tid = threadIdx.x;
    const float* a  = A  + (size_t)row*D_MODEL;
    const float* bb = Bm + (size_t)row*D_MODEL;
    float v[4];
    float s = 0.f;
    #pragma unroll
    for (int i = 0; i < 4; i++) { int c = tid + i*256; v[i] = a[c] + bb[c]; s += v[i]; }
    #pragma unroll
    for (int o = 16; o; o >>= 1) s += __shfl_xor_sync(0xffffffffu, s, o);
    if ((tid & 31) == 0) sh[tid >> 5] = s;
    __syncthreads();
    float tot = 0.f;
    #pragma unroll
    for (int i = 0; i < 8; i++) tot += sh[i];
    const float mean = tot * (1.f/(float)D_MODEL);
    float s2 = 0.f;
    #pragma unroll
    for (int i = 0; i < 4; i++) { float d = v[i]-mean; s2 += d*d; }
    #pragma unroll
    for (int o = 16; o; o >>= 1) s2 += __shfl_xor_sync(0xffffffffu, s2, o);
    __syncthreads();
    if ((tid & 31) == 0) sh[tid >> 5] = s2;
    __syncthreads();
    float tot2 = 0.f;
    #pragma unroll
    for (int i = 0; i < 8; i++) tot2 += sh[i];
    const float inv = 1.f / (sqrtf(tot2 * (1.f/(float)D_MODEL)) + LN_EPS);
    #pragma unroll
    for (int i = 0; i < 4; i++) {
        int c = tid + i*256;
        float r = gamma[c]*(v[i]-mean)*inv + beta[c];
        out[(size_t)row*D_MODEL + c] = r;
        if (SPLIT) {
            __nv_bfloat16 h = __float2bfloat16(r);
            oh[(size_t)row*D_MODEL + c] = h;
            ol[(size_t)row*D_MODEL + c] = __float2bfloat16(r - __bfloat162float(h));
        }
    }
}

// ================= launcher =================
extern "C" void kernel_launch(void* const* d_in, const int* in_sizes, int n_in,
                              void* d_out, int out_size)
{
    const float* x   = (const float*)d_in[0];
    const float* Wq  = (const float*)d_in[1];
    const float* bq  = (const float*)d_in[2];
    const float* Wk  = (const float*)d_in[3];
    const float* bk  = (const float*)d_in[4];
    const float* Wv  = (const float*)d_in[5];
    const float* bv  = (const float*)d_in[6];
    const float* Wo  = (const float*)d_in[7];
    const float* bo  = (const float*)d_in[8];
    const float* W1  = (const float*)d_in[9];
    const float* b1  = (const float*)d_in[10];
    const float* W2  = (const float*)d_in[11];
    const float* b2  = (const float*)d_in[12];
    const float* g1  = (const float*)d_in[13];
    const float* be1 = (const float*)d_in[14];
    const float* g2  = (const float*)d_in[15];
    const float* be2 = (const float*)d_in[16];
    float* out = (float*)d_out;

    float *Q,*Kb,*V,*t1,*h;
    __nv_bfloat16 *xh,*xl,*ch,*cl,*hh,*hl,*f1h,*f1l;
    __nv_bfloat16 *wqh,*wql,*wkh,*wkl,*wvh,*wvl,*woh,*wol,*w1h,*w1l,*w2h,*w2l;
    cudaGetSymbolAddress((void**)&Q,   g_Q);   cudaGetSymbolAddress((void**)&Kb,  g_K);
    cudaGetSymbolAddress((void**)&V,   g_V);   cudaGetSymbolAddress((void**)&t1,  g_t1);
    cudaGetSymbolAddress((void**)&h,   g_h);
    cudaGetSymbolAddress((void**)&xh,  g_xh);  cudaGetSymbolAddress((void**)&xl,  g_xl);
    cudaGetSymbolAddress((void**)&ch,  g_ch);  cudaGetSymbolAddress((void**)&cl,  g_cl);
    cudaGetSymbolAddress((void**)&hh,  g_hh);  cudaGetSymbolAddress((void**)&hl,  g_hl);
    cudaGetSymbolAddress((void**)&f1h, g_f1h); cudaGetSymbolAddress((void**)&f1l, g_f1l);
    cudaGetSymbolAddress((void**)&wqh, g_wqh); cudaGetSymbolAddress((void**)&wql, g_wql);
    cudaGetSymbolAddress((void**)&wkh, g_wkh); cudaGetSymbolAddress((void**)&wkl, g_wkl);
    cudaGetSymbolAddress((void**)&wvh, g_wvh); cudaGetSymbolAddress((void**)&wvl, g_wvl);
    cudaGetSymbolAddress((void**)&woh, g_woh); cudaGetSymbolAddress((void**)&wol, g_wol);
    cudaGetSymbolAddress((void**)&w1h, g_w1h); cudaGetSymbolAddress((void**)&w1l, g_w1l);
    cudaGetSymbolAddress((void**)&w2h, g_w2h); cudaGetSymbolAddress((void**)&w2l, g_w2l);

    cudaFuncSetAttribute(gemm_mma<0>, cudaFuncAttributeMaxDynamicSharedMemorySize, GEMM_SMEM);
    cudaFuncSetAttribute(gemm_mma<1>, cudaFuncAttributeMaxDynamicSharedMemorySize, GEMM_SMEM);
    cudaFuncSetAttribute(attention_kernel, cudaFuncAttributeMaxDynamicSharedMemorySize, ATT_SMEM_BYTES);

    const int nX = NROWS*D_MODEL;
    split_f32_kernel<<<nX/1024, 256>>>(x, xh, xl, nX);
    dim3 tt(32, 8);
    transpose_split_kernel<<<dim3(D_MODEL/32, D_MODEL/32), tt>>>(Wq, wqh, wql, D_MODEL, D_MODEL);
    transpose_split_kernel<<<dim3(D_MODEL/32, D_MODEL/32), tt>>>(Wk, wkh, wkl, D_MODEL, D_MODEL);
    transpose_split_kernel<<<dim3(D_MODEL/32, D_MODEL/32), tt>>>(Wv, wvh, wvl, D_MODEL, D_MODEL);
    transpose_split_kernel<<<dim3(D_MODEL/32, D_MODEL/32), tt>>>(Wo, woh, wol, D_MODEL, D_MODEL);
    transpose_split_kernel<<<dim3(D_FF/32,    D_MODEL/32), tt>>>(W1, w1h, w1l, D_MODEL, D_FF);
    transpose_split_kernel<<<dim3(D_MODEL/32, D_FF/32),    tt>>>(W2, w2h, w2l, D_FF, D_MODEL);

    dim3 thr(256);
    // QKV
    gemm_mma<0><<<dim3(8, 32), thr, GEMM_SMEM>>>(xh, xl, wqh, wql, bq, Q,  nullptr, nullptr, D_MODEL, D_MODEL);
    gemm_mma<0><<<dim3(8, 32), thr, GEMM_SMEM>>>(xh, xl, wkh, wkl, bk, Kb, nullptr, nullptr, D_MODEL, D_MODEL);
    gemm_mma<0><<<dim3(8, 32), thr, GEMM_SMEM>>>(xh, xl, wvh, wvl, bv, V,  nullptr, nullptr, D_MODEL, D_MODEL);
    // attention
    attention_kernel<<<dim3(SEQ/64, BATCH*NHEADS), thr, ATT_SMEM_BYTES>>>(Q, Kb, V, ch, cl);
    // Wo + LN1
    gemm_mma<0><<<dim3(8, 32), thr, GEMM_SMEM>>>(ch, cl, woh, wol, bo, t1, nullptr, nullptr, D_MODEL, D_MODEL);
    add_ln_kernel<true><<<NROWS, thr>>>(x, t1, g1, be1, h, hh, hl);
    // FFN
    gemm_mma<1><<<dim3(32, 32), thr, GEMM_SMEM>>>(hh, hl, w1h, w1l, b1, nullptr, f1h, f1l, D_MODEL, D_FF);
    gemm_mma<0><<<dim3(8, 32), thr, GEMM_SMEM>>>(f1h, f1l, w2h, w2l, b2, t1, nullptr, nullptr, D_FF, D_MODEL);
    add_ln_kernel<false><<<NROWS, thr>>>(h, t1, g2, be2, out, nullptr, nullptr);
}

// round 5
// speedup vs baseline: 2.3872x; 1.5302x over previous
#include <cuda_runtime.h>
#include <cuda_bf16.h>
#include <math.h>
#include <stdint.h>

#define D_MODEL 1024
#define NHEADS  16
#define DKH     64
#define D_FF    4096
#define BATCH   2
#define SEQ     2048
#define NROWS   (BATCH*SEQ)
#define LN_EPS  1e-6f

#define SWZ128(x) ((x) ^ (((x) >> 3) & 0x70))

// ================= PTX helpers (sm_80+ subset, legal on sm_100) ============
__device__ __forceinline__ uint32_t smem_u32(const void* p) {
    uint32_t a;
    asm("{ .reg .u64 t; cvta.to.shared.u64 t, %1; cvt.u32.u64 %0, t; }" : "=r"(a) : "l"(p));
    return a;
}
__device__ __forceinline__ void ldsm_x4(uint32_t& r0, uint32_t& r1, uint32_t& r2, uint32_t& r3, uint32_t addr) {
    asm volatile("ldmatrix.sync.aligned.m8n8.x4.shared.b16 {%0,%1,%2,%3}, [%4];"
                 : "=r"(r0), "=r"(r1), "=r"(r2), "=r"(r3) : "r"(addr));
}
__device__ __forceinline__ void ldsm_x4_t(uint32_t& r0, uint32_t& r1, uint32_t& r2, uint32_t& r3, uint32_t addr) {
    asm volatile("ldmatrix.sync.aligned.m8n8.x4.trans.shared.b16 {%0,%1,%2,%3}, [%4];"
                 : "=r"(r0), "=r"(r1), "=r"(r2), "=r"(r3) : "r"(addr));
}
__device__ __forceinline__ void mma_bf16(float* c, uint32_t a0, uint32_t a1, uint32_t a2, uint32_t a3,
                                         uint32_t b0, uint32_t b1) {
    asm volatile(
        "mma.sync.aligned.m16n8k16.row.col.f32.bf16.bf16.f32 "
        "{%0,%1,%2,%3}, {%4,%5,%6,%7}, {%8,%9}, {%0,%1,%2,%3};"
        : "+f"(c[0]), "+f"(c[1]), "+f"(c[2]), "+f"(c[3])
        : "r"(a0), "r"(a1), "r"(a2), "r"(a3), "r"(b0), "r"(b1));
}
__device__ __forceinline__ void cp16(uint32_t saddr, const void* gptr) {
    asm volatile("cp.async.cg.shared.global [%0], [%1], 16;" :: "r"(saddr), "l"(gptr));
}
#define CP_COMMIT() asm volatile("cp.async.commit_group;" ::: "memory")
#define CP_WAIT(n)  asm volatile("cp.async.wait_group %0;" :: "n"(n) : "memory")
__device__ __forceinline__ float ex2f(float x) { float y; asm("ex2.approx.f32 %0, %1;" : "=f"(y) : "f"(x)); return y; }
__device__ __forceinline__ uint32_t pack_bf2(float a, float b) {
    __nv_bfloat16 ha = __float2bfloat16(a), hb = __float2bfloat16(b);
    return (uint32_t)__bfloat16_as_ushort(ha) | ((uint32_t)__bfloat16_as_ushort(hb) << 16);
}
__device__ __forceinline__ uint32_t pack_bf2_res(float a, float b, uint32_t hp) {
    float ra = a - __bfloat162float(__ushort_as_bfloat16((unsigned short)(hp & 0xffff)));
    float rb = b - __bfloat162float(__ushort_as_bfloat16((unsigned short)(hp >> 16)));
    return pack_bf2(ra, rb);
}

// ================= scratch =================
__device__ float g_Q [(size_t)NROWS*D_MODEL];
__device__ float g_t1[(size_t)NROWS*D_MODEL];
__device__ float g_h [(size_t)NROWS*D_MODEL];

__device__ __nv_bfloat16 g_xh [(size_t)NROWS*D_MODEL], g_xl [(size_t)NROWS*D_MODEL];
__device__ __nv_bfloat16 g_kh [(size_t)NROWS*D_MODEL], g_kl [(size_t)NROWS*D_MODEL];
__device__ __nv_bfloat16 g_vh [(size_t)NROWS*D_MODEL], g_vl [(size_t)NROWS*D_MODEL];
__device__ __nv_bfloat16 g_ch [(size_t)NROWS*D_MODEL], g_cl [(size_t)NROWS*D_MODEL];
__device__ __nv_bfloat16 g_hh [(size_t)NROWS*D_MODEL], g_hl [(size_t)NROWS*D_MODEL];
__device__ __nv_bfloat16 g_f1h[(size_t)NROWS*D_FF],    g_f1l[(size_t)NROWS*D_FF];
__device__ __nv_bfloat16 g_wqh[(size_t)D_MODEL*D_MODEL], g_wql[(size_t)D_MODEL*D_MODEL];
__device__ __nv_bfloat16 g_wkh[(size_t)D_MODEL*D_MODEL], g_wkl[(size_t)D_MODEL*D_MODEL];
__device__ __nv_bfloat16 g_wvh[(size_t)D_MODEL*D_MODEL], g_wvl[(size_t)D_MODEL*D_MODEL];
__device__ __nv_bfloat16 g_woh[(size_t)D_MODEL*D_MODEL], g_wol[(size_t)D_MODEL*D_MODEL];
__device__ __nv_bfloat16 g_w1h[(size_t)D_FF*D_MODEL],    g_w1l[(size_t)D_FF*D_MODEL];
__device__ __nv_bfloat16 g_w2h[(size_t)D_MODEL*D_FF],    g_w2l[(size_t)D_MODEL*D_FF];

// ================= conversion kernels =================
__global__ __launch_bounds__(256)
void split_f32_kernel(const float* __restrict__ in, __nv_bfloat16* __restrict__ hi,
                      __nv_bfloat16* __restrict__ lo, int n)
{
    int i = (blockIdx.x * 256 + threadIdx.x) * 4;
    if (i >= n) return;
    float4 v = *(const float4*)(in + i);
    float vv[4] = {v.x, v.y, v.z, v.w};
    #pragma unroll
    for (int j = 0; j < 4; j++) {
        __nv_bfloat16 h = __float2bfloat16(vv[j]);
        hi[i+j] = h;
        lo[i+j] = __float2bfloat16(vv[j] - __bfloat162float(h));
    }
}

__global__ __launch_bounds__(256)
void transpose_split_kernel(const float* __restrict__ W, __nv_bfloat16* __restrict__ Th,
                            __nv_bfloat16* __restrict__ Tl, int K, int M)
{
    __shared__ float ts[32][33];
    const int m0 = blockIdx.x * 32, k0 = blockIdx.y * 32;
    const int tx = threadIdx.x, ty = threadIdx.y;
    #pragma unroll
    for (int i = 0; i < 4; i++) {
        int k = ty + i*8;
        ts[k][tx] = W[(size_t)(k0+k)*M + m0 + tx];
    }
    __syncthreads();
    #pragma unroll
    for (int i = 0; i < 4; i++) {
        int m = ty + i*8;
        float v = ts[tx][m];
        __nv_bfloat16 h = __float2bfloat16(v);
        size_t o = (size_t)(m0+m)*K + k0 + tx;
        Th[o] = h;
        Tl[o] = __float2bfloat16(v - __bfloat162float(h));
    }
}

// ================= mma.sync split-bf16 GEMM ================================
// MODE 0: f32 out. MODE 1: relu + split out. MODE 2: split out (no relu).
#define GEMM_SMEM (2*65536)

template<int MODE>
__global__ __launch_bounds__(256)
void gemm_mma(const __nv_bfloat16* __restrict__ Ah, const __nv_bfloat16* __restrict__ Al,
              const __nv_bfloat16* __restrict__ Bh, const __nv_bfloat16* __restrict__ Bl,
              const float* __restrict__ bias,
              float* __restrict__ Cf, __nv_bfloat16* __restrict__ Ch, __nv_bfloat16* __restrict__ Cl,
              int K, int M)
{
    extern __shared__ char sb[];
    const int tid  = threadIdx.x;
    const int wid  = tid >> 5;
    const int lane = tid & 31;
    const int wm   = wid >> 2;
    const int wn   = wid & 3;
    const int brow = blockIdx.y * 128;
    const int bcol = blockIdx.x * 128;
    const uint32_t sbu = smem_u32(sb);

    float acc[4][4][4];
    #pragma unroll
    for (int mf = 0; mf < 4; mf++)
      #pragma unroll
      for (int nf = 0; nf < 4; nf++)
        #pragma unroll
        for (int q = 0; q < 4; q++) acc[mf][nf][q] = 0.f;

    const int NC = K >> 6;
    const __nv_bfloat16* srcs[4] = {Ah, Al, Bh, Bl};
    const int bases[4] = {brow, brow, bcol, bcol};

    {
        #pragma unroll
        for (int it = 0; it < 16; it++) {
            int idx  = tid + it*256;
            int tile = idx >> 10;
            int rem  = idx & 1023;
            int r    = rem >> 3;
            int chn  = rem & 7;
            const __nv_bfloat16* g = srcs[tile] + (size_t)(bases[tile] + r)*K + chn*8;
            uint32_t so = (uint32_t)tile*16384u + SWZ128((uint32_t)((r << 7) + (chn << 4)));
            cp16(sbu + so, g);
        }
        CP_COMMIT();
    }

    for (int c = 0; c < NC; c++) {
        if (c + 1 < NC) {
            const int kc = (c+1) << 6;
            const uint32_t boff = (uint32_t)((c+1) & 1) * 65536u;
            #pragma unroll
            for (int it = 0; it < 16; it++) {
                int idx  = tid + it*256;
                int tile = idx >> 10;
                int rem  = idx & 1023;
                int r    = rem >> 3;
                int chn  = rem & 7;
                const __nv_bfloat16* g = srcs[tile] + (size_t)(bases[tile] + r)*K + kc + chn*8;
                uint32_t so = boff + (uint32_t)tile*16384u + SWZ128((uint32_t)((r << 7) + (chn << 4)));
                cp16(sbu + so, g);
            }
            CP_COMMIT();
            CP_WAIT(1);
        } else {
            CP_WAIT(0);
        }
        __syncthreads();

        const uint32_t buf = sbu + (uint32_t)(c & 1) * 65536u;
        const uint32_t aHb = buf;
        const uint32_t aLb = buf + 16384u;
        const uint32_t bHb = buf + 32768u;
        const uint32_t bLb = buf + 49152u;

        const int rloc   = (lane & 7) + ((lane >> 3) & 1) * 8;
        const int kpiece = (lane >> 4) << 4;

        #pragma unroll
        for (int ks = 0; ks < 4; ks++) {
            const uint32_t wb = (uint32_t)(ks*32 + kpiece);
            uint32_t ah[4][4], al[4][4];
            #pragma unroll
            for (int mf = 0; mf < 4; mf++) {
                uint32_t off = SWZ128((uint32_t)(((wm*64 + mf*16 + rloc) << 7)) + wb);
                ldsm_x4(ah[mf][0], ah[mf][1], ah[mf][2], ah[mf][3], aHb + off);
                ldsm_x4(al[mf][0], al[mf][1], al[mf][2], al[mf][3], aLb + off);
            }
            uint32_t bh[2][4], bl[2][4];
            #pragma unroll
            for (int g = 0; g < 2; g++) {
                uint32_t off = SWZ128((uint32_t)(((wn*32 + g*16 + rloc) << 7)) + wb);
                ldsm_x4(bh[g][0], bh[g][1], bh[g][2], bh[g][3], bHb + off);
                ldsm_x4(bl[g][0], bl[g][1], bl[g][2], bl[g][3], bLb + off);
            }
            #pragma unroll
            for (int mf = 0; mf < 4; mf++) {
                #pragma unroll
                for (int g = 0; g < 2; g++) {
                    #pragma unroll
                    for (int s = 0; s < 2; s++) {
                        const int nf = g*2 + s;
                        uint32_t bh0 = s ? bh[g][1] : bh[g][0];
                        uint32_t bh1 = s ? bh[g][3] : bh[g][2];
                        uint32_t bl0 = s ? bl[g][1] : bl[g][0];
                        uint32_t bl1 = s ? bl[g][3] : bl[g][2];
                        mma_bf16(acc[mf][nf], ah[mf][0], ah[mf][1], ah[mf][2], ah[mf][3], bh0, bh1);
                        mma_bf16(acc[mf][nf], ah[mf][0], ah[mf][1], ah[mf][2], ah[mf][3], bl0, bl1);
                        mma_bf16(acc[mf][nf], al[mf][0], al[mf][1], al[mf][2], al[mf][3], bh0, bh1);
                    }
                }
            }
        }
        __syncthreads();
    }

    const int qr = lane >> 2;
    const int qc = (lane & 3) * 2;
    #pragma unroll
    for (int mf = 0; mf < 4; mf++) {
        #pragma unroll
        for (int nf = 0; nf < 4; nf++) {
            const int row = brow + wm*64 + mf*16 + qr;
            const int col = bcol + wn*32 + nf*8 + qc;
            const float b0 = __ldg(bias + col), b1 = __ldg(bias + col + 1);
            float v00 = acc[mf][nf][0] + b0, v01 = acc[mf][nf][1] + b1;
            float v10 = acc[mf][nf][2] + b0, v11 = acc[mf][nf][3] + b1;
            if (MODE == 0) {
                *(float2*)(Cf + (size_t)row*M + col)     = make_float2(v00, v01);
                *(float2*)(Cf + (size_t)(row+8)*M + col) = make_float2(v10, v11);
            } else {
                if (MODE == 1) {
                    v00 = fmaxf(v00, 0.f); v01 = fmaxf(v01, 0.f);
                    v10 = fmaxf(v10, 0.f); v11 = fmaxf(v11, 0.f);
                }
                uint32_t hp0 = pack_bf2(v00, v01), hp1 = pack_bf2(v10, v11);
                uint32_t lp0 = pack_bf2_res(v00, v01, hp0), lp1 = pack_bf2_res(v10, v11, hp1);
                *(uint32_t*)(Ch + (size_t)row*M + col)     = hp0;
                *(uint32_t*)(Ch + (size_t)(row+8)*M + col) = hp1;
                *(uint32_t*)(Cl + (size_t)row*M + col)     = lp0;
                *(uint32_t*)(Cl + (size_t)(row+8)*M + col) = lp1;
            }
        }
    }
}

// ================= mma.sync flash attention ================================
// BQ=128, BK=64, dk=64. 8 warps; warp w owns query rows w*16..w*16+15.
// Smem: Q hi/lo (2x16KB) + 2 KV buffers x (Kh,Kl,Vh,Vl each 8KB) = 96KB.
#define ATT_SMEM (32768 + 2*32768)

__global__ __launch_bounds__(256)
void attention_mma(const float* __restrict__ Q,
                   const __nv_bfloat16* __restrict__ Kh, const __nv_bfloat16* __restrict__ Kl,
                   const __nv_bfloat16* __restrict__ Vh, const __nv_bfloat16* __restrict__ Vl,
                   __nv_bfloat16* __restrict__ ctxh, __nv_bfloat16* __restrict__ ctxl)
{
    extern __shared__ char sb[];
    const uint32_t sbu = smem_u32(sb);
    const int tid  = threadIdx.x;
    const int wid  = tid >> 5;
    const int lane = tid & 31;
    const int bh   = blockIdx.y;
    const int b    = bh >> 4;
    const int hh   = bh & 15;
    const int q0   = blockIdx.x * 128;
    const size_t rbase = (size_t)b*SEQ*D_MODEL + (size_t)hh*DKH;

    // ---- load Q (scaled by 1/8 * log2(e)) into split-bf16 smem ----
    const float qscale = 0.125f * 1.44269504f;
    #pragma unroll
    for (int i = 0; i < 16; i++) {
        int p  = tid + i*256;          // pair index 0..4095
        int r  = p >> 5, c2 = p & 31;
        float2 v = *(const float2*)(Q + rbase + (size_t)(q0+r)*D_MODEL + c2*2);
        v.x *= qscale; v.y *= qscale;
        uint32_t hp = pack_bf2(v.x, v.y);
        uint32_t lp = pack_bf2_res(v.x, v.y, hp);
        uint32_t off = SWZ128((uint32_t)((r << 7) + (c2 << 2)));
        *(uint32_t*)(sb + off)          = hp;
        *(uint32_t*)(sb + 16384u + off) = lp;
    }
    __syncthreads();

    const int rloc   = (lane & 7) + ((lane >> 3) & 1) * 8;
    const int kpiece = (lane >> 4) << 4;

    // ---- hoist Q fragments (invariant over key tiles) ----
    uint32_t qh[4][4], ql[4][4];
    #pragma unroll
    for (int ks = 0; ks < 4; ks++) {
        uint32_t off = SWZ128((uint32_t)(((wid*16 + rloc) << 7) + ks*32 + kpiece));
        ldsm_x4(qh[ks][0], qh[ks][1], qh[ks][2], qh[ks][3], sbu + off);
        ldsm_x4(ql[ks][0], ql[ks][1], ql[ks][2], ql[ks][3], sbu + 16384u + off);
    }

    float O[8][4];
    #pragma unroll
    for (int nt = 0; nt < 8; nt++)
      #pragma unroll
      for (int q = 0; q < 4; q++) O[nt][q] = 0.f;
    float m0 = -1e30f, m1 = -1e30f, l0 = 0.f, l1 = 0.f;

    const __nv_bfloat16* kvsrc[4] = {Kh, Kl, Vh, Vl};
    const int NT = SEQ / 64;

    // prefetch tile 0
    {
        #pragma unroll
        for (int it = 0; it < 8; it++) {
            int idx  = tid + it*256;      // 0..2047
            int tile = idx >> 9;
            int rem  = idx & 511;
            int r    = rem >> 3;
            int c8   = rem & 7;
            const __nv_bfloat16* g = kvsrc[tile] + rbase + (size_t)r*D_MODEL + c8*8;
            cp16(sbu + 32768u + (uint32_t)tile*8192u + SWZ128((uint32_t)((r << 7) + (c8 << 4))), g);
        }
        CP_COMMIT();
    }

    for (int t = 0; t < NT; t++) {
        if (t + 1 < NT) {
            const int s0 = (t+1) * 64;
            const uint32_t boff = 32768u + (uint32_t)((t+1) & 1) * 32768u;
            #pragma unroll
            for (int it = 0; it < 8; it++) {
                int idx  = tid + it*256;
                int tile = idx >> 9;
                int rem  = idx & 511;
                int r    = rem >> 3;
                int c8   = rem & 7;
                const __nv_bfloat16* g = kvsrc[tile] + rbase + (size_t)(s0+r)*D_MODEL + c8*8;
                cp16(sbu + boff + (uint32_t)tile*8192u + SWZ128((uint32_t)((r << 7) + (c8 << 4))), g);
            }
            CP_COMMIT();
            CP_WAIT(1);
        } else {
            CP_WAIT(0);
        }
        __syncthreads();

        const uint32_t kb = sbu + 32768u + (uint32_t)(t & 1) * 32768u;

        // ---- S = Q K^T (log2-domain prescaled) ----
        float sc[8][4];
        #pragma unroll
        for (int nt = 0; nt < 8; nt++)
          #pragma unroll
          for (int q = 0; q < 4; q++) sc[nt][q] = 0.f;

        #pragma unroll
        for (int ks = 0; ks < 4; ks++) {
            #pragma unroll
            for (int g = 0; g < 4; g++) {
                uint32_t kf[4], lf[4];
                uint32_t off = SWZ128((uint32_t)(((g*16 + rloc) << 7) + ks*32 + kpiece));
                ldsm_x4(kf[0], kf[1], kf[2], kf[3], kb + off);
                ldsm_x4(lf[0], lf[1], lf[2], lf[3], kb + 8192u + off);
                #pragma unroll
                for (int s = 0; s < 2; s++) {
                    const int nt = g*2 + s;
                    uint32_t b0 = s ? kf[1] : kf[0];
                    uint32_t b1 = s ? kf[3] : kf[2];
                    uint32_t c0 = s ? lf[1] : lf[0];
                    uint32_t c1 = s ? lf[3] : lf[2];
                    mma_bf16(sc[nt], qh[ks][0], qh[ks][1], qh[ks][2], qh[ks][3], b0, b1);
                    mma_bf16(sc[nt], qh[ks][0], qh[ks][1], qh[ks][2], qh[ks][3], c0, c1);
                    mma_bf16(sc[nt], ql[ks][0], ql[ks][1], ql[ks][2], ql[ks][3], b0, b1);
                }
            }
        }

        // ---- online softmax (base-2), rows owned in-warp ----
        float mx0 = -1e30f, mx1 = -1e30f;
        #pragma unroll
        for (int nt = 0; nt < 8; nt++) {
            mx0 = fmaxf(mx0, fmaxf(sc[nt][0], sc[nt][1]));
            mx1 = fmaxf(mx1, fmaxf(sc[nt][2], sc[nt][3]));
        }
        mx0 = fmaxf(mx0, __shfl_xor_sync(0xffffffffu, mx0, 1));
        mx0 = fmaxf(mx0, __shfl_xor_sync(0xffffffffu, mx0, 2));
        mx1 = fmaxf(mx1, __shfl_xor_sync(0xffffffffu, mx1, 1));
        mx1 = fmaxf(mx1, __shfl_xor_sync(0xffffffffu, mx1, 2));
        const float mn0 = fmaxf(m0, mx0), mn1 = fmaxf(m1, mx1);
        const float a0 = ex2f(m0 - mn0), a1 = ex2f(m1 - mn1);
        float s0 = 0.f, s1 = 0.f;
        #pragma unroll
        for (int nt = 0; nt < 8; nt++) {
            sc[nt][0] = ex2f(sc[nt][0] - mn0);
            sc[nt][1] = ex2f(sc[nt][1] - mn0);
            sc[nt][2] = ex2f(sc[nt][2] - mn1);
            sc[nt][3] = ex2f(sc[nt][3] - mn1);
            s0 += sc[nt][0] + sc[nt][1];
            s1 += sc[nt][2] + sc[nt][3];
        }
        s0 += __shfl_xor_sync(0xffffffffu, s0, 1);
        s0 += __shfl_xor_sync(0xffffffffu, s0, 2);
        s1 += __shfl_xor_sync(0xffffffffu, s1, 1);
        s1 += __shfl_xor_sync(0xffffffffu, s1, 2);
        l0 = l0*a0 + s0; l1 = l1*a1 + s1;
        m0 = mn0; m1 = mn1;
        #pragma unroll
        for (int nt = 0; nt < 8; nt++) {
            O[nt][0] *= a0; O[nt][1] *= a0;
            O[nt][2] *= a1; O[nt][3] *= a1;
        }

        // ---- O += P V  (P split from registers, V via ldmatrix.trans) ----
        const uint32_t vb = kb + 16384u;
        #pragma unroll
        for (int ks = 0; ks < 4; ks++) {
            const int e = 2*ks, o = 2*ks + 1;
            uint32_t ah0 = pack_bf2(sc[e][0], sc[e][1]);
            uint32_t ah1 = pack_bf2(sc[e][2], sc[e][3]);
            uint32_t ah2 = pack_bf2(sc[o][0], sc[o][1]);
            uint32_t ah3 = pack_bf2(sc[o][2], sc[o][3]);
            uint32_t al0 = pack_bf2_res(sc[e][0], sc[e][1], ah0);
            uint32_t al1 = pack_bf2_res(sc[e][2], sc[e][3], ah1);
            uint32_t al2 = pack_bf2_res(sc[o][0], sc[o][1], ah2);
            uint32_t al3 = pack_bf2_res(sc[o][2], sc[o][3], ah3);
            #pragma unroll
            for (int dg = 0; dg < 4; dg++) {
                uint32_t vf[4], wf[4];
                uint32_t off = SWZ128((uint32_t)(((ks*16 + rloc) << 7) + dg*32 + kpiece));
                ldsm_x4_t(vf[0], vf[1], vf[2], vf[3], vb + off);
                ldsm_x4_t(wf[0], wf[1], wf[2], wf[3], vb + 8192u + off);
                mma_bf16(O[dg*2],   ah0, ah1, ah2, ah3, vf[0], vf[1]);
                mma_bf16(O[dg*2],   ah0, ah1, ah2, ah3, wf[0], wf[1]);
                mma_bf16(O[dg*2],   al0, al1, al2, al3, vf[0], vf[1]);
                mma_bf16(O[dg*2+1], ah0, ah1, ah2, ah3, vf[2], vf[3]);
                mma_bf16(O[dg*2+1], ah0, ah1, ah2, ah3, wf[2], wf[3]);
                mma_bf16(O[dg*2+1], al0, al1, al2, al3, vf[2], vf[3]);
            }
        }
        __syncthreads();
    }

    // ---- epilogue: normalize, split-bf16 write ----
    const float i0 = 1.f / l0, i1 = 1.f / l1;
    const int qr = lane >> 2;
    const int qc = (lane & 3) * 2;
    const int rowA = q0 + wid*16 + qr;
    #pragma unroll
    for (int nt = 0; nt < 8; nt++) {
        float v0 = O[nt][0]*i0, v1 = O[nt][1]*i0;
        float v2 = O[nt][2]*i1, v3 = O[nt][3]*i1;
        size_t oA = rbase + (size_t)rowA*D_MODEL + nt*8 + qc;
        size_t oB = oA + 8*D_MODEL;
        uint32_t hpA = pack_bf2(v0, v1), hpB = pack_bf2(v2, v3);
        *(uint32_t*)(ctxh + oA) = hpA;
        *(uint32_t*)(ctxh + oB) = hpB;
        *(uint32_t*)(ctxl + oA) = pack_bf2_res(v0, v1, hpA);
        *(uint32_t*)(ctxl + oB) = pack_bf2_res(v2, v3, hpB);
    }
}

// ================= residual add + LayerNorm ================================
template<bool SPLIT>
__global__ __launch_bounds__(256)
void add_ln_kernel(const float* __restrict__ A, const float* __restrict__ Bm,
                   const float* __restrict__ gamma, const float* __restrict__ beta,
                   float* __restrict__ out, __nv_bfloat16* __restrict__ oh,
                   __nv_bfloat16* __restrict__ ol)
{
    __shared__ float sh[8];
    const int row = blockIdx.x;
    const int tid = threadIdx.x;
    const float* a  = A  + (size_t)row*D_MODEL;
    const float* bb = Bm + (size_t)row*D_MODEL;
    float v[4];
    float s = 0.f;
    #pragma unroll
    for (int i = 0; i < 4; i++) { int c = tid + i*256; v[i] = a[c] + bb[c]; s += v[i]; }
    #pragma unroll
    for (int o = 16; o; o >>= 1) s += __shfl_xor_sync(0xffffffffu, s, o);
    if ((tid & 31) == 0) sh[tid >> 5] = s;
    __syncthreads();
    float tot = 0.f;
    #pragma unroll
    for (int i = 0; i < 8; i++) tot += sh[i];
    const float mean = tot * (1.f/(float)D_MODEL);
    float s2 = 0.f;
    #pragma unroll
    for (int i = 0; i < 4; i++) { float d = v[i]-mean; s2 += d*d; }
    #pragma unroll
    for (int o = 16; o; o >>= 1) s2 += __shfl_xor_sync(0xffffffffu, s2, o);
    __syncthreads();
    if ((tid & 31) == 0) sh[tid >> 5] = s2;
    __syncthreads();
    float tot2 = 0.f;
    #pragma unroll
    for (int i = 0; i < 8; i++) tot2 += sh[i];
    const float inv = 1.f / (sqrtf(tot2 * (1.f/(float)D_MODEL)) + LN_EPS);
    #pragma unroll
    for (int i = 0; i < 4; i++) {
        int c = tid + i*256;
        float r = gamma[c]*(v[i]-mean)*inv + beta[c];
        out[(size_t)row*D_MODEL + c] = r;
        if (SPLIT) {
            __nv_bfloat16 h = __float2bfloat16(r);
            oh[(size_t)row*D_MODEL + c] = h;
            ol[(size_t)row*D_MODEL + c] = __float2bfloat16(r - __bfloat162float(h));
        }
    }
}

// ================= launcher =================
extern "C" void kernel_launch(void* const* d_in, const int* in_sizes, int n_in,
                              void* d_out, int out_size)
{
    const float* x   = (const float*)d_in[0];
    const float* Wq  = (const float*)d_in[1];
    const float* bq  = (const float*)d_in[2];
    const float* Wk  = (const float*)d_in[3];
    const float* bk  = (const float*)d_in[4];
    const float* Wv  = (const float*)d_in[5];
    const float* bv  = (const float*)d_in[6];
    const float* Wo  = (const float*)d_in[7];
    const float* bo  = (const float*)d_in[8];
    const float* W1  = (const float*)d_in[9];
    const float* b1  = (const float*)d_in[10];
    const float* W2  = (const float*)d_in[11];
    const float* b2  = (const float*)d_in[12];
    const float* g1  = (const float*)d_in[13];
    const float* be1 = (const float*)d_in[14];
    const float* g2  = (const float*)d_in[15];
    const float* be2 = (const float*)d_in[16];
    float* out = (float*)d_out;

    float *Q,*t1,*h;
    __nv_bfloat16 *xh,*xl,*kh,*kl,*vh,*vl,*ch,*cl,*hh,*hl,*f1h,*f1l;
    __nv_bfloat16 *wqh,*wql,*wkh,*wkl,*wvh,*wvl,*woh,*wol,*w1h,*w1l,*w2h,*w2l;
    cudaGetSymbolAddress((void**)&Q,   g_Q);   cudaGetSymbolAddress((void**)&t1,  g_t1);
    cudaGetSymbolAddress((void**)&h,   g_h);
    cudaGetSymbolAddress((void**)&xh,  g_xh);  cudaGetSymbolAddress((void**)&xl,  g_xl);
    cudaGetSymbolAddress((void**)&kh,  g_kh);  cudaGetSymbolAddress((void**)&kl,  g_kl);
    cudaGetSymbolAddress((void**)&vh,  g_vh);  cudaGetSymbolAddress((void**)&vl,  g_vl);
    cudaGetSymbolAddress((void**)&ch,  g_ch);  cudaGetSymbolAddress((void**)&cl,  g_cl);
    cudaGetSymbolAddress((void**)&hh,  g_hh);  cudaGetSymbolAddress((void**)&hl,  g_hl);
    cudaGetSymbolAddress((void**)&f1h, g_f1h); cudaGetSymbolAddress((void**)&f1l, g_f1l);
    cudaGetSymbolAddress((void**)&wqh, g_wqh); cudaGetSymbolAddress((void**)&wql, g_wql);
    cudaGetSymbolAddress((void**)&wkh, g_wkh); cudaGetSymbolAddress((void**)&wkl, g_wkl);
    cudaGetSymbolAddress((void**)&wvh, g_wvh); cudaGetSymbolAddress((void**)&wvl, g_wvl);
    cudaGetSymbolAddress((void**)&woh, g_woh); cudaGetSymbolAddress((void**)&wol, g_wol);
    cudaGetSymbolAddress((void**)&w1h, g_w1h); cudaGetSymbolAddress((void**)&w1l, g_w1l);
    cudaGetSymbolAddress((void**)&w2h, g_w2h); cudaGetSymbolAddress((void**)&w2l, g_w2l);

    cudaFuncSetAttribute(gemm_mma<0>, cudaFuncAttributeMaxDynamicSharedMemorySize, GEMM_SMEM);
    cudaFuncSetAttribute(gemm_mma<1>, cudaFuncAttributeMaxDynamicSharedMemorySize, GEMM_SMEM);
    cudaFuncSetAttribute(gemm_mma<2>, cudaFuncAttributeMaxDynamicSharedMemorySize, GEMM_SMEM);
    cudaFuncSetAttribute(attention_mma, cudaFuncAttributeMaxDynamicSharedMemorySize, ATT_SMEM);

    const int nX = NROWS*D_MODEL;
    split_f32_kernel<<<nX/1024, 256>>>(x, xh, xl, nX);
    dim3 tt(32, 8);
    transpose_split_kernel<<<dim3(D_MODEL/32, D_MODEL/32), tt>>>(Wq, wqh, wql, D_MODEL, D_MODEL);
    transpose_split_kernel<<<dim3(D_MODEL/32, D_MODEL/32), tt>>>(Wk, wkh, wkl, D_MODEL, D_MODEL);
    transpose_split_kernel<<<dim3(D_MODEL/32, D_MODEL/32), tt>>>(Wv, wvh, wvl, D_MODEL, D_MODEL);
    transpose_split_kernel<<<dim3(D_MODEL/32, D_MODEL/32), tt>>>(Wo, woh, wol, D_MODEL, D_MODEL);
    transpose_split_kernel<<<dim3(D_FF/32,    D_MODEL/32), tt>>>(W1, w1h, w1l, D_MODEL, D_FF);
    transpose_split_kernel<<<dim3(D_MODEL/32, D_FF/32),    tt>>>(W2, w2h, w2l, D_FF, D_MODEL);

    dim3 thr(256);
    // QKV: Q -> fp32, K/V -> split bf16
    gemm_mma<0><<<dim3(8, 32), thr, GEMM_SMEM>>>(xh, xl, wqh, wql, bq, Q,  nullptr, nullptr, D_MODEL, D_MODEL);
    gemm_mma<2><<<dim3(8, 32), thr, GEMM_SMEM>>>(xh, xl, wkh, wkl, bk, nullptr, kh, kl, D_MODEL, D_MODEL);
    gemm_mma<2><<<dim3(8, 32), thr, GEMM_SMEM>>>(xh, xl, wvh, wvl, bv, nullptr, vh, vl, D_MODEL, D_MODEL);
    // attention (tensor-core)
    attention_mma<<<dim3(SEQ/128, BATCH*NHEADS), thr, ATT_SMEM>>>(Q, kh, kl, vh, vl, ch, cl);
    // Wo + LN1
    gemm_mma<0><<<dim3(8, 32), thr, GEMM_SMEM>>>(ch, cl, woh, wol, bo, t1, nullptr, nullptr, D_MODEL, D_MODEL);
    add_ln_kernel<true><<<NROWS, thr>>>(x, t1, g1, be1, h, hh, hl);
    // FFN
    gemm_mma<1><<<dim3(32, 32), thr, GEMM_SMEM>>>(hh, hl, w1h, w1l, b1, nullptr, f1h, f1l, D_MODEL, D_FF);
    gemm_mma<0><<<dim3(8, 32), thr, GEMM_SMEM>>>(f1h, f1l, w2h, w2l, b2, t1, nullptr, nullptr, D_FF, D_MODEL);
    add_ln_kernel<false><<<NROWS, thr>>>(h, t1, g2, be2, out, nullptr, nullptr);
}

// round 6
// speedup vs baseline: 2.3976x; 1.0044x over previous
#include <cuda_runtime.h>
#include <cuda_bf16.h>
#include <math.h>
#include <stdint.h>

#define D_MODEL 1024
#define NHEADS  16
#define DKH     64
#define D_FF    4096
#define BATCH   2
#define SEQ     2048
#define NROWS   (BATCH*SEQ)
#define LN_EPS  1e-6f

#define SWZ128(x) ((x) ^ (((x) >> 3) & 0x70))

// ================= PTX helpers (sm_80+ subset, legal on sm_100) ============
__device__ __forceinline__ uint32_t smem_u32(const void* p) {
    uint32_t a;
    asm("{ .reg .u64 t; cvta.to.shared.u64 t, %1; cvt.u32.u64 %0, t; }" : "=r"(a) : "l"(p));
    return a;
}
__device__ __forceinline__ void ldsm_x4(uint32_t& r0, uint32_t& r1, uint32_t& r2, uint32_t& r3, uint32_t addr) {
    asm volatile("ldmatrix.sync.aligned.m8n8.x4.shared.b16 {%0,%1,%2,%3}, [%4];"
                 : "=r"(r0), "=r"(r1), "=r"(r2), "=r"(r3) : "r"(addr));
}
__device__ __forceinline__ void ldsm_x4_t(uint32_t& r0, uint32_t& r1, uint32_t& r2, uint32_t& r3, uint32_t addr) {
    asm volatile("ldmatrix.sync.aligned.m8n8.x4.trans.shared.b16 {%0,%1,%2,%3}, [%4];"
                 : "=r"(r0), "=r"(r1), "=r"(r2), "=r"(r3) : "r"(addr));
}
__device__ __forceinline__ void mma_bf16(float* c, uint32_t a0, uint32_t a1, uint32_t a2, uint32_t a3,
                                         uint32_t b0, uint32_t b1) {
    asm volatile(
        "mma.sync.aligned.m16n8k16.row.col.f32.bf16.bf16.f32 "
        "{%0,%1,%2,%3}, {%4,%5,%6,%7}, {%8,%9}, {%0,%1,%2,%3};"
        : "+f"(c[0]), "+f"(c[1]), "+f"(c[2]), "+f"(c[3])
        : "r"(a0), "r"(a1), "r"(a2), "r"(a3), "r"(b0), "r"(b1));
}
__device__ __forceinline__ void cp16(uint32_t saddr, const void* gptr) {
    asm volatile("cp.async.cg.shared.global [%0], [%1], 16;" :: "r"(saddr), "l"(gptr));
}
#define CP_COMMIT() asm volatile("cp.async.commit_group;" ::: "memory")
#define CP_WAIT(n)  asm volatile("cp.async.wait_group %0;" :: "n"(n) : "memory")
__device__ __forceinline__ float ex2f(float x) { float y; asm("ex2.approx.f32 %0, %1;" : "=f"(y) : "f"(x)); return y; }
__device__ __forceinline__ uint32_t pack_bf2(float a, float b) {
    __nv_bfloat16 ha = __float2bfloat16(a), hb = __float2bfloat16(b);
    return (uint32_t)__bfloat16_as_ushort(ha) | ((uint32_t)__bfloat16_as_ushort(hb) << 16);
}
__device__ __forceinline__ uint32_t pack_bf2_res(float a, float b, uint32_t hp) {
    float ra = a - __bfloat162float(__ushort_as_bfloat16((unsigned short)(hp & 0xffff)));
    float rb = b - __bfloat162float(__ushort_as_bfloat16((unsigned short)(hp >> 16)));
    return pack_bf2(ra, rb);
}

// ================= scratch =================
__device__ float g_Q [(size_t)NROWS*D_MODEL];
__device__ float g_t1[(size_t)NROWS*D_MODEL];
__device__ float g_h [(size_t)NROWS*D_MODEL];

__device__ __nv_bfloat16 g_xh [(size_t)NROWS*D_MODEL], g_xl [(size_t)NROWS*D_MODEL];
__device__ __nv_bfloat16 g_kh [(size_t)NROWS*D_MODEL], g_kl [(size_t)NROWS*D_MODEL];
__device__ __nv_bfloat16 g_vh [(size_t)NROWS*D_MODEL], g_vl [(size_t)NROWS*D_MODEL];
__device__ __nv_bfloat16 g_ch [(size_t)NROWS*D_MODEL], g_cl [(size_t)NROWS*D_MODEL];
__device__ __nv_bfloat16 g_hh [(size_t)NROWS*D_MODEL], g_hl [(size_t)NROWS*D_MODEL];
__device__ __nv_bfloat16 g_f1h[(size_t)NROWS*D_FF],    g_f1l[(size_t)NROWS*D_FF];
__device__ __nv_bfloat16 g_wqkvh[(size_t)3*D_MODEL*D_MODEL], g_wqkvl[(size_t)3*D_MODEL*D_MODEL]; // fused [3072,1024]
__device__ __nv_bfloat16 g_woh[(size_t)D_MODEL*D_MODEL], g_wol[(size_t)D_MODEL*D_MODEL];
__device__ __nv_bfloat16 g_w1h[(size_t)D_FF*D_MODEL],    g_w1l[(size_t)D_FF*D_MODEL];
__device__ __nv_bfloat16 g_w2h[(size_t)D_MODEL*D_FF],    g_w2l[(size_t)D_MODEL*D_FF];

// ================= conversion kernels =================
__global__ __launch_bounds__(256)
void split_f32_kernel(const float* __restrict__ in, __nv_bfloat16* __restrict__ hi,
                      __nv_bfloat16* __restrict__ lo, int n)
{
    int i = (blockIdx.x * 256 + threadIdx.x) * 4;
    if (i >= n) return;
    float4 v = *(const float4*)(in + i);
    float vv[4] = {v.x, v.y, v.z, v.w};
    #pragma unroll
    for (int j = 0; j < 4; j++) {
        __nv_bfloat16 h = __float2bfloat16(vv[j]);
        hi[i+j] = h;
        lo[i+j] = __float2bfloat16(vv[j] - __bfloat162float(h));
    }
}

// W [K, M] f32 -> T(hi/lo)[rowoff + m, k] bf16
__global__ __launch_bounds__(256)
void transpose_split_kernel(const float* __restrict__ W, __nv_bfloat16* __restrict__ Th,
                            __nv_bfloat16* __restrict__ Tl, int K, int M, int rowoff)
{
    __shared__ float ts[32][33];
    const int m0 = blockIdx.x * 32, k0 = blockIdx.y * 32;
    const int tx = threadIdx.x, ty = threadIdx.y;
    #pragma unroll
    for (int i = 0; i < 4; i++) {
        int k = ty + i*8;
        ts[k][tx] = W[(size_t)(k0+k)*M + m0 + tx];
    }
    __syncthreads();
    #pragma unroll
    for (int i = 0; i < 4; i++) {
        int m = ty + i*8;
        float v = ts[tx][m];
        __nv_bfloat16 h = __float2bfloat16(v);
        size_t o = (size_t)(rowoff + m0 + m)*K + k0 + tx;
        Th[o] = h;
        Tl[o] = __float2bfloat16(v - __bfloat162float(h));
    }
}

// ================= mma.sync split-bf16 GEMM ================================
// MODE 0: f32 out. MODE 1: relu + split out. MODE 2: split out (no relu).
// MODE 3: fused QKV — section 0 (cols 0-1023) f32 -> Cf; section 1 -> Ch/Cl;
//         section 2 -> C2h/C2l. Per-section bias. Output stride D_MODEL.
#define GEMM_SMEM (2*65536)

template<int MODE>
__global__ __launch_bounds__(256)
void gemm_mma(const __nv_bfloat16* __restrict__ Ah, const __nv_bfloat16* __restrict__ Al,
              const __nv_bfloat16* __restrict__ Bh, const __nv_bfloat16* __restrict__ Bl,
              const float* __restrict__ bias, const float* __restrict__ bias2,
              const float* __restrict__ bias3,
              float* __restrict__ Cf, __nv_bfloat16* __restrict__ Ch, __nv_bfloat16* __restrict__ Cl,
              __nv_bfloat16* __restrict__ C2h, __nv_bfloat16* __restrict__ C2l,
              int K, int M)
{
    extern __shared__ char sb[];
    const int tid  = threadIdx.x;
    const int wid  = tid >> 5;
    const int lane = tid & 31;
    const int wm   = wid >> 2;
    const int wn   = wid & 3;
    const int brow = blockIdx.y * 128;
    const int bcol = blockIdx.x * 128;
    const uint32_t sbu = smem_u32(sb);

    float acc[4][4][4];
    #pragma unroll
    for (int mf = 0; mf < 4; mf++)
      #pragma unroll
      for (int nf = 0; nf < 4; nf++)
        #pragma unroll
        for (int q = 0; q < 4; q++) acc[mf][nf][q] = 0.f;

    const int NC = K >> 6;
    const __nv_bfloat16* srcs[4] = {Ah, Al, Bh, Bl};
    const int bases[4] = {brow, brow, bcol, bcol};

    {
        #pragma unroll
        for (int it = 0; it < 16; it++) {
            int idx  = tid + it*256;
            int tile = idx >> 10;
            int rem  = idx & 1023;
            int r    = rem >> 3;
            int chn  = rem & 7;
            const __nv_bfloat16* g = srcs[tile] + (size_t)(bases[tile] + r)*K + chn*8;
            uint32_t so = (uint32_t)tile*16384u + SWZ128((uint32_t)((r << 7) + (chn << 4)));
            cp16(sbu + so, g);
        }
        CP_COMMIT();
    }

    for (int c = 0; c < NC; c++) {
        if (c + 1 < NC) {
            const int kc = (c+1) << 6;
            const uint32_t boff = (uint32_t)((c+1) & 1) * 65536u;
            #pragma unroll
            for (int it = 0; it < 16; it++) {
                int idx  = tid + it*256;
                int tile = idx >> 10;
                int rem  = idx & 1023;
                int r    = rem >> 3;
                int chn  = rem & 7;
                const __nv_bfloat16* g = srcs[tile] + (size_t)(bases[tile] + r)*K + kc + chn*8;
                uint32_t so = boff + (uint32_t)tile*16384u + SWZ128((uint32_t)((r << 7) + (chn << 4)));
                cp16(sbu + so, g);
            }
            CP_COMMIT();
            CP_WAIT(1);
        } else {
            CP_WAIT(0);
        }
        __syncthreads();

        const uint32_t buf = sbu + (uint32_t)(c & 1) * 65536u;
        const uint32_t aHb = buf;
        const uint32_t aLb = buf + 16384u;
        const uint32_t bHb = buf + 32768u;
        const uint32_t bLb = buf + 49152u;

        const int rloc   = (lane & 7) + ((lane >> 3) & 1) * 8;
        const int kpiece = (lane >> 4) << 4;

        #pragma unroll
        for (int ks = 0; ks < 4; ks++) {
            const uint32_t wb = (uint32_t)(ks*32 + kpiece);
            uint32_t ah[4][4], al[4][4];
            #pragma unroll
            for (int mf = 0; mf < 4; mf++) {
                uint32_t off = SWZ128((uint32_t)(((wm*64 + mf*16 + rloc) << 7)) + wb);
                ldsm_x4(ah[mf][0], ah[mf][1], ah[mf][2], ah[mf][3], aHb + off);
                ldsm_x4(al[mf][0], al[mf][1], al[mf][2], al[mf][3], aLb + off);
            }
            uint32_t bh[2][4], bl[2][4];
            #pragma unroll
            for (int g = 0; g < 2; g++) {
                uint32_t off = SWZ128((uint32_t)(((wn*32 + g*16 + rloc) << 7)) + wb);
                ldsm_x4(bh[g][0], bh[g][1], bh[g][2], bh[g][3], bHb + off);
                ldsm_x4(bl[g][0], bl[g][1], bl[g][2], bl[g][3], bLb + off);
            }
            #pragma unroll
            for (int mf = 0; mf < 4; mf++) {
                #pragma unroll
                for (int g = 0; g < 2; g++) {
                    #pragma unroll
                    for (int s = 0; s < 2; s++) {
                        const int nf = g*2 + s;
                        uint32_t bh0 = s ? bh[g][1] : bh[g][0];
                        uint32_t bh1 = s ? bh[g][3] : bh[g][2];
                        uint32_t bl0 = s ? bl[g][1] : bl[g][0];
                        uint32_t bl1 = s ? bl[g][3] : bl[g][2];
                        mma_bf16(acc[mf][nf], ah[mf][0], ah[mf][1], ah[mf][2], ah[mf][3], bh0, bh1);
                        mma_bf16(acc[mf][nf], ah[mf][0], ah[mf][1], ah[mf][2], ah[mf][3], bl0, bl1);
                        mma_bf16(acc[mf][nf], al[mf][0], al[mf][1], al[mf][2], al[mf][3], bh0, bh1);
                    }
                }
            }
        }
        __syncthreads();
    }

    const int qr = lane >> 2;
    const int qc = (lane & 3) * 2;

    // section select for MODE 3 (all 128 CTA cols in one 1024-col section)
    int sec = 0;
    const float* bi = bias;
    float*         Df  = Cf;
    __nv_bfloat16 *Dh  = Ch, *Dl = Cl;
    int ostride = M;
    if (MODE == 3) {
        sec = bcol >> 10;
        bi  = (sec == 0) ? bias : (sec == 1 ? bias2 : bias3);
        Dh  = (sec == 2) ? C2h : Ch;
        Dl  = (sec == 2) ? C2l : Cl;
        ostride = D_MODEL;
    }

    #pragma unroll
    for (int mf = 0; mf < 4; mf++) {
        #pragma unroll
        for (int nf = 0; nf < 4; nf++) {
            const int row  = brow + wm*64 + mf*16 + qr;
            const int col  = bcol + wn*32 + nf*8 + qc;
            const int colS = (MODE == 3) ? (col & 1023) : col;
            const float b0 = __ldg(bi + colS), b1 = __ldg(bi + colS + 1);
            float v00 = acc[mf][nf][0] + b0, v01 = acc[mf][nf][1] + b1;
            float v10 = acc[mf][nf][2] + b0, v11 = acc[mf][nf][3] + b1;
            bool wf32 = (MODE == 0) || (MODE == 3 && sec == 0);
            if (wf32) {
                *(float2*)(Df + (size_t)row*ostride + colS)     = make_float2(v00, v01);
                *(float2*)(Df + (size_t)(row+8)*ostride + colS) = make_float2(v10, v11);
            } else {
                if (MODE == 1) {
                    v00 = fmaxf(v00, 0.f); v01 = fmaxf(v01, 0.f);
                    v10 = fmaxf(v10, 0.f); v11 = fmaxf(v11, 0.f);
                }
                uint32_t hp0 = pack_bf2(v00, v01), hp1 = pack_bf2(v10, v11);
                uint32_t lp0 = pack_bf2_res(v00, v01, hp0), lp1 = pack_bf2_res(v10, v11, hp1);
                *(uint32_t*)(Dh + (size_t)row*ostride + colS)     = hp0;
                *(uint32_t*)(Dh + (size_t)(row+8)*ostride + colS) = hp1;
                *(uint32_t*)(Dl + (size_t)row*ostride + colS)     = lp0;
                *(uint32_t*)(Dl + (size_t)(row+8)*ostride + colS) = lp1;
            }
        }
    }
}

// ================= mma.sync flash attention ================================
// BQ=128, BK=64, dk=64. 8 warps; warp w owns query rows w*16..w*16+15.
#define ATT_SMEM (32768 + 2*32768)

__global__ __launch_bounds__(256)
void attention_mma(const float* __restrict__ Q,
                   const __nv_bfloat16* __restrict__ Kh, const __nv_bfloat16* __restrict__ Kl,
                   const __nv_bfloat16* __restrict__ Vh, const __nv_bfloat16* __restrict__ Vl,
                   __nv_bfloat16* __restrict__ ctxh, __nv_bfloat16* __restrict__ ctxl)
{
    extern __shared__ char sb[];
    const uint32_t sbu = smem_u32(sb);
    const int tid  = threadIdx.x;
    const int wid  = tid >> 5;
    const int lane = tid & 31;
    const int bh   = blockIdx.y;
    const int b    = bh >> 4;
    const int hh   = bh & 15;
    const int q0   = blockIdx.x * 128;
    const size_t rbase = (size_t)b*SEQ*D_MODEL + (size_t)hh*DKH;

    const float qscale = 0.125f * 1.44269504f;
    #pragma unroll
    for (int i = 0; i < 16; i++) {
        int p  = tid + i*256;
        int r  = p >> 5, c2 = p & 31;
        float2 v = *(const float2*)(Q + rbase + (size_t)(q0+r)*D_MODEL + c2*2);
        v.x *= qscale; v.y *= qscale;
        uint32_t hp = pack_bf2(v.x, v.y);
        uint32_t lp = pack_bf2_res(v.x, v.y, hp);
        uint32_t off = SWZ128((uint32_t)((r << 7) + (c2 << 2)));
        *(uint32_t*)(sb + off)          = hp;
        *(uint32_t*)(sb + 16384u + off) = lp;
    }
    __syncthreads();

    const int rloc   = (lane & 7) + ((lane >> 3) & 1) * 8;
    const int kpiece = (lane >> 4) << 4;

    uint32_t qh[4][4], ql[4][4];
    #pragma unroll
    for (int ks = 0; ks < 4; ks++) {
        uint32_t off = SWZ128((uint32_t)(((wid*16 + rloc) << 7) + ks*32 + kpiece));
        ldsm_x4(qh[ks][0], qh[ks][1], qh[ks][2], qh[ks][3], sbu + off);
        ldsm_x4(ql[ks][0], ql[ks][1], ql[ks][2], ql[ks][3], sbu + 16384u + off);
    }

    float O[8][4];
    #pragma unroll
    for (int nt = 0; nt < 8; nt++)
      #pragma unroll
      for (int q = 0; q < 4; q++) O[nt][q] = 0.f;
    float m0 = -1e30f, m1 = -1e30f, l0 = 0.f, l1 = 0.f;

    const __nv_bfloat16* kvsrc[4] = {Kh, Kl, Vh, Vl};
    const int NT = SEQ / 64;

    {
        #pragma unroll
        for (int it = 0; it < 8; it++) {
            int idx  = tid + it*256;
            int tile = idx >> 9;
            int rem  = idx & 511;
            int r    = rem >> 3;
            int c8   = rem & 7;
            const __nv_bfloat16* g = kvsrc[tile] + rbase + (size_t)r*D_MODEL + c8*8;
            cp16(sbu + 32768u + (uint32_t)tile*8192u + SWZ128((uint32_t)((r << 7) + (c8 << 4))), g);
        }
        CP_COMMIT();
    }

    for (int t = 0; t < NT; t++) {
        if (t + 1 < NT) {
            const int s0 = (t+1) * 64;
            const uint32_t boff = 32768u + (uint32_t)((t+1) & 1) * 32768u;
            #pragma unroll
            for (int it = 0; it < 8; it++) {
                int idx  = tid + it*256;
                int tile = idx >> 9;
                int rem  = idx & 511;
                int r    = rem >> 3;
                int c8   = rem & 7;
                const __nv_bfloat16* g = kvsrc[tile] + rbase + (size_t)(s0+r)*D_MODEL + c8*8;
                cp16(sbu + boff + (uint32_t)tile*8192u + SWZ128((uint32_t)((r << 7) + (c8 << 4))), g);
            }
            CP_COMMIT();
            CP_WAIT(1);
        } else {
            CP_WAIT(0);
        }
        __syncthreads();

        const uint32_t kb = sbu + 32768u + (uint32_t)(t & 1) * 32768u;

        float sc[8][4];
        #pragma unroll
        for (int nt = 0; nt < 8; nt++)
          #pragma unroll
          for (int q = 0; q < 4; q++) sc[nt][q] = 0.f;

        #pragma unroll
        for (int ks = 0; ks < 4; ks++) {
            #pragma unroll
            for (int g = 0; g < 4; g++) {
                uint32_t kf[4], lf[4];
                uint32_t off = SWZ128((uint32_t)(((g*16 + rloc) << 7) + ks*32 + kpiece));
                ldsm_x4(kf[0], kf[1], kf[2], kf[3], kb + off);
                ldsm_x4(lf[0], lf[1], lf[2], lf[3], kb + 8192u + off);
                #pragma unroll
                for (int s = 0; s < 2; s++) {
                    const int nt = g*2 + s;
                    uint32_t b0 = s ? kf[1] : kf[0];
                    uint32_t b1 = s ? kf[3] : kf[2];
                    uint32_t c0 = s ? lf[1] : lf[0];
                    uint32_t c1 = s ? lf[3] : lf[2];
                    mma_bf16(sc[nt], qh[ks][0], qh[ks][1], qh[ks][2], qh[ks][3], b0, b1);
                    mma_bf16(sc[nt], qh[ks][0], qh[ks][1], qh[ks][2], qh[ks][3], c0, c1);
                    mma_bf16(sc[nt], ql[ks][0], ql[ks][1], ql[ks][2], ql[ks][3], b0, b1);
                }
            }
        }

        float mx0 = -1e30f, mx1 = -1e30f;
        #pragma unroll
        for (int nt = 0; nt < 8; nt++) {
            mx0 = fmaxf(mx0, fmaxf(sc[nt][0], sc[nt][1]));
            mx1 = fmaxf(mx1, fmaxf(sc[nt][2], sc[nt][3]));
        }
        mx0 = fmaxf(mx0, __shfl_xor_sync(0xffffffffu, mx0, 1));
        mx0 = fmaxf(mx0, __shfl_xor_sync(0xffffffffu, mx0, 2));
        mx1 = fmaxf(mx1, __shfl_xor_sync(0xffffffffu, mx1, 1));
        mx1 = fmaxf(mx1, __shfl_xor_sync(0xffffffffu, mx1, 2));
        const float mn0 = fmaxf(m0, mx0), mn1 = fmaxf(m1, mx1);
        const float a0 = ex2f(m0 - mn0), a1 = ex2f(m1 - mn1);
        float s0 = 0.f, s1 = 0.f;
        #pragma unroll
        for (int nt = 0; nt < 8; nt++) {
            sc[nt][0] = ex2f(sc[nt][0] - mn0);
            sc[nt][1] = ex2f(sc[nt][1] - mn0);
            sc[nt][2] = ex2f(sc[nt][2] - mn1);
            sc[nt][3] = ex2f(sc[nt][3] - mn1);
            s0 += sc[nt][0] + sc[nt][1];
            s1 += sc[nt][2] + sc[nt][3];
        }
        s0 += __shfl_xor_sync(0xffffffffu, s0, 1);
        s0 += __shfl_xor_sync(0xffffffffu, s0, 2);
        s1 += __shfl_xor_sync(0xffffffffu, s1, 1);
        s1 += __shfl_xor_sync(0xffffffffu, s1, 2);
        l0 = l0*a0 + s0; l1 = l1*a1 + s1;
        m0 = mn0; m1 = mn1;
        #pragma unroll
        for (int nt = 0; nt < 8; nt++) {
            O[nt][0] *= a0; O[nt][1] *= a0;
            O[nt][2] *= a1; O[nt][3] *= a1;
        }

        const uint32_t vb = kb + 16384u;
        #pragma unroll
        for (int ks = 0; ks < 4; ks++) {
            const int e = 2*ks, o = 2*ks + 1;
            uint32_t ah0 = pack_bf2(sc[e][0], sc[e][1]);
            uint32_t ah1 = pack_bf2(sc[e][2], sc[e][3]);
            uint32_t ah2 = pack_bf2(sc[o][0], sc[o][1]);
            uint32_t ah3 = pack_bf2(sc[o][2], sc[o][3]);
            uint32_t al0 = pack_bf2_res(sc[e][0], sc[e][1], ah0);
            uint32_t al1 = pack_bf2_res(sc[e][2], sc[e][3], ah1);
            uint32_t al2 = pack_bf2_res(sc[o][0], sc[o][1], ah2);
            uint32_t al3 = pack_bf2_res(sc[o][2], sc[o][3], ah3);
            #pragma unroll
            for (int dg = 0; dg < 4; dg++) {
                uint32_t vf[4], wf[4];
                uint32_t off = SWZ128((uint32_t)(((ks*16 + rloc) << 7) + dg*32 + kpiece));
                ldsm_x4_t(vf[0], vf[1], vf[2], vf[3], vb + off);
                ldsm_x4_t(wf[0], wf[1], wf[2], wf[3], vb + 8192u + off);
                mma_bf16(O[dg*2],   ah0, ah1, ah2, ah3, vf[0], vf[1]);
                mma_bf16(O[dg*2],   ah0, ah1, ah2, ah3, wf[0], wf[1]);
                mma_bf16(O[dg*2],   al0, al1, al2, al3, vf[0], vf[1]);
                mma_bf16(O[dg*2+1], ah0, ah1, ah2, ah3, vf[2], vf[3]);
                mma_bf16(O[dg*2+1], ah0, ah1, ah2, ah3, wf[2], wf[3]);
                mma_bf16(O[dg*2+1], al0, al1, al2, al3, vf[2], vf[3]);
            }
        }
        __syncthreads();
    }

    const float i0 = 1.f / l0, i1 = 1.f / l1;
    const int qr = lane >> 2;
    const int qc = (lane & 3) * 2;
    const int rowA = q0 + wid*16 + qr;
    #pragma unroll
    for (int nt = 0; nt < 8; nt++) {
        float v0 = O[nt][0]*i0, v1 = O[nt][1]*i0;
        float v2 = O[nt][2]*i1, v3 = O[nt][3]*i1;
        size_t oA = rbase + (size_t)rowA*D_MODEL + nt*8 + qc;
        size_t oB = oA + 8*D_MODEL;
        uint32_t hpA = pack_bf2(v0, v1), hpB = pack_bf2(v2, v3);
        *(uint32_t*)(ctxh + oA) = hpA;
        *(uint32_t*)(ctxh + oB) = hpB;
        *(uint32_t*)(ctxl + oA) = pack_bf2_res(v0, v1, hpA);
        *(uint32_t*)(ctxl + oB) = pack_bf2_res(v2, v3, hpB);
    }
}

// ================= residual add + LayerNorm ================================
template<bool SPLIT>
__global__ __launch_bounds__(256)
void add_ln_kernel(const float* __restrict__ A, const float* __restrict__ Bm,
                   const float* __restrict__ gamma, const float* __restrict__ beta,
                   float* __restrict__ out, __nv_bfloat16* __restrict__ oh,
                   __nv_bfloat16* __restrict__ ol)
{
    __shared__ float sh[8];
    const int row = blockIdx.x;
    const int tid = threadIdx.x;
    const float* a  = A  + (size_t)row*D_MODEL;
    const float* bb = Bm + (size_t)row*D_MODEL;
    float v[4];
    float s = 0.f;
    #pragma unroll
    for (int i = 0; i < 4; i++) { int c = tid + i*256; v[i] = a[c] + bb[c]; s += v[i]; }
    #pragma unroll
    for (int o = 16; o; o >>= 1) s += __shfl_xor_sync(0xffffffffu, s, o);
    if ((tid & 31) == 0) sh[tid >> 5] = s;
    __syncthreads();
    float tot = 0.f;
    #pragma unroll
    for (int i = 0; i < 8; i++) tot += sh[i];
    const float mean = tot * (1.f/(float)D_MODEL);
    float s2 = 0.f;
    #pragma unroll
    for (int i = 0; i < 4; i++) { float d = v[i]-mean; s2 += d*d; }
    #pragma unroll
    for (int o = 16; o; o >>= 1) s2 += __shfl_xor_sync(0xffffffffu, s2, o);
    __syncthreads();
    if ((tid & 31) == 0) sh[tid >> 5] = s2;
    __syncthreads();
    float tot2 = 0.f;
    #pragma unroll
    for (int i = 0; i < 8; i++) tot2 += sh[i];
    const float inv = 1.f / (sqrtf(tot2 * (1.f/(float)D_MODEL)) + LN_EPS);
    #pragma unroll
    for (int i = 0; i < 4; i++) {
        int c = tid + i*256;
        float r = gamma[c]*(v[i]-mean)*inv + beta[c];
        out[(size_t)row*D_MODEL + c] = r;
        if (SPLIT) {
            __nv_bfloat16 h = __float2bfloat16(r);
            oh[(size_t)row*D_MODEL + c] = h;
            ol[(size_t)row*D_MODEL + c] = __float2bfloat16(r - __bfloat162float(h));
        }
    }
}

// ================= launcher =================
extern "C" void kernel_launch(void* const* d_in, const int* in_sizes, int n_in,
                              void* d_out, int out_size)
{
    const float* x   = (const float*)d_in[0];
    const float* Wq  = (const float*)d_in[1];
    const float* bq  = (const float*)d_in[2];
    const float* Wk  = (const float*)d_in[3];
    const float* bk  = (const float*)d_in[4];
    const float* Wv  = (const float*)d_in[5];
    const float* bv  = (const float*)d_in[6];
    const float* Wo  = (const float*)d_in[7];
    const float* bo  = (const float*)d_in[8];
    const float* W1  = (const float*)d_in[9];
    const float* b1  = (const float*)d_in[10];
    const float* W2  = (const float*)d_in[11];
    const float* b2  = (const float*)d_in[12];
    const float* g1  = (const float*)d_in[13];
    const float* be1 = (const float*)d_in[14];
    const float* g2  = (const float*)d_in[15];
    const float* be2 = (const float*)d_in[16];
    float* out = (float*)d_out;

    float *Q,*t1,*h;
    __nv_bfloat16 *xh,*xl,*kh,*kl,*vh,*vl,*ch,*cl,*hh,*hl,*f1h,*f1l;
    __nv_bfloat16 *wqkvh,*wqkvl,*woh,*wol,*w1h,*w1l,*w2h,*w2l;
    cudaGetSymbolAddress((void**)&Q,     g_Q);     cudaGetSymbolAddress((void**)&t1,    g_t1);
    cudaGetSymbolAddress((void**)&h,     g_h);
    cudaGetSymbolAddress((void**)&xh,    g_xh);    cudaGetSymbolAddress((void**)&xl,    g_xl);
    cudaGetSymbolAddress((void**)&kh,    g_kh);    cudaGetSymbolAddress((void**)&kl,    g_kl);
    cudaGetSymbolAddress((void**)&vh,    g_vh);    cudaGetSymbolAddress((void**)&vl,    g_vl);
    cudaGetSymbolAddress((void**)&ch,    g_ch);    cudaGetSymbolAddress((void**)&cl,    g_cl);
    cudaGetSymbolAddress((void**)&hh,    g_hh);    cudaGetSymbolAddress((void**)&hl,    g_hl);
    cudaGetSymbolAddress((void**)&f1h,   g_f1h);   cudaGetSymbolAddress((void**)&f1l,   g_f1l);
    cudaGetSymbolAddress((void**)&wqkvh, g_wqkvh); cudaGetSymbolAddress((void**)&wqkvl, g_wqkvl);
    cudaGetSymbolAddress((void**)&woh,   g_woh);   cudaGetSymbolAddress((void**)&wol,   g_wol);
    cudaGetSymbolAddress((void**)&w1h,   g_w1h);   cudaGetSymbolAddress((void**)&w1l,   g_w1l);
    cudaGetSymbolAddress((void**)&w2h,   g_w2h);   cudaGetSymbolAddress((void**)&w2l,   g_w2l);

    cudaFuncSetAttribute(gemm_mma<0>, cudaFuncAttributeMaxDynamicSharedMemorySize, GEMM_SMEM);
    cudaFuncSetAttribute(gemm_mma<1>, cudaFuncAttributeMaxDynamicSharedMemorySize, GEMM_SMEM);
    cudaFuncSetAttribute(gemm_mma<3>, cudaFuncAttributeMaxDynamicSharedMemorySize, GEMM_SMEM);
    cudaFuncSetAttribute(attention_mma, cudaFuncAttributeMaxDynamicSharedMemorySize, ATT_SMEM);

    const int nX = NROWS*D_MODEL;
    dim3 tt(32, 8);
    dim3 thr(256);

    // launch idx 0
    split_f32_kernel<<<nX/1024, 256>>>(x, xh, xl, nX);
    // idx 1-3: QKV weight transposes into fused [3072,1024] buffer
    transpose_split_kernel<<<dim3(D_MODEL/32, D_MODEL/32), tt>>>(Wq, wqkvh, wqkvl, D_MODEL, D_MODEL, 0);
    transpose_split_kernel<<<dim3(D_MODEL/32, D_MODEL/32), tt>>>(Wk, wqkvh, wqkvl, D_MODEL, D_MODEL, D_MODEL);
    transpose_split_kernel<<<dim3(D_MODEL/32, D_MODEL/32), tt>>>(Wv, wqkvh, wqkvl, D_MODEL, D_MODEL, 2*D_MODEL);
    // idx 4
    transpose_split_kernel<<<dim3(D_MODEL/32, D_MODEL/32), tt>>>(Wo, woh, wol, D_MODEL, D_MODEL, 0);
    // idx 5: fused QKV GEMM  <-- ncu -s 5 captures this
    gemm_mma<3><<<dim3(24, 32), thr, GEMM_SMEM>>>(xh, xl, wqkvh, wqkvl, bq, bk, bv,
                                                  Q, kh, kl, vh, vl, D_MODEL, D_MODEL);
    // idx 6: attention
    attention_mma<<<dim3(SEQ/128, BATCH*NHEADS), thr, ATT_SMEM>>>(Q, kh, kl, vh, vl, ch, cl);
    // idx 7: Wo
    gemm_mma<0><<<dim3(8, 32), thr, GEMM_SMEM>>>(ch, cl, woh, wol, bo, nullptr, nullptr,
                                                 t1, nullptr, nullptr, nullptr, nullptr, D_MODEL, D_MODEL);
    // idx 8: LN1
    add_ln_kernel<true><<<NROWS, thr>>>(x, t1, g1, be1, h, hh, hl);
    // idx 9-10: FFN weight transposes (deferred; only needed from idx 11)
    transpose_split_kernel<<<dim3(D_FF/32,    D_MODEL/32), tt>>>(W1, w1h, w1l, D_MODEL, D_FF, 0);
    transpose_split_kernel<<<dim3(D_MODEL/32, D_FF/32),    tt>>>(W2, w2h, w2l, D_FF, D_MODEL, 0);
    // idx 11: FF1 (relu, split out)
    gemm_mma<1><<<dim3(32, 32), thr, GEMM_SMEM>>>(hh, hl, w1h, w1l, b1, nullptr, nullptr,
                                                  nullptr, f1h, f1l, nullptr, nullptr, D_MODEL, D_FF);
    // idx 12: FF2
    gemm_mma<0><<<dim3(8, 32), thr, GEMM_SMEM>>>(f1h, f1l, w2h, w2l, b2, nullptr, nullptr,
                                                 t1, nullptr, nullptr, nullptr, nullptr, D_FF, D_MODEL);
    // idx 13: LN2
    add_ln_kernel<false><<<NROWS, thr>>>(h, t1, g2, be2, out, nullptr, nullptr);
}

// round 8
// speedup vs baseline: 6.3726x; 2.6579x over previous
#include <cuda_runtime.h>
#include <cuda_fp16.h>
#include <math.h>
#include <stdint.h>

#define D_MODEL 1024
#define NHEADS  16
#define DKH     64
#define D_FF    4096
#define BATCH   2
#define SEQ     2048
#define NROWS   (BATCH*SEQ)
#define LN_EPS  1e-6f

#define SWZ128(x) ((x) ^ (((x) >> 3) & 0x70))

// ================= PTX helpers ============================================
__device__ __forceinline__ uint32_t smem_u32(const void* p) {
    uint32_t a;
    asm("{ .reg .u64 t; cvta.to.shared.u64 t, %1; cvt.u32.u64 %0, t; }" : "=r"(a) : "l"(p));
    return a;
}
__device__ __forceinline__ void ldsm_x4(uint32_t& r0, uint32_t& r1, uint32_t& r2, uint32_t& r3, uint32_t addr) {
    asm volatile("ldmatrix.sync.aligned.m8n8.x4.shared.b16 {%0,%1,%2,%3}, [%4];"
                 : "=r"(r0), "=r"(r1), "=r"(r2), "=r"(r3) : "r"(addr));
}
__device__ __forceinline__ void ldsm_x4_t(uint32_t& r0, uint32_t& r1, uint32_t& r2, uint32_t& r3, uint32_t addr) {
    asm volatile("ldmatrix.sync.aligned.m8n8.x4.trans.shared.b16 {%0,%1,%2,%3}, [%4];"
                 : "=r"(r0), "=r"(r1), "=r"(r2), "=r"(r3) : "r"(addr));
}
__device__ __forceinline__ void mma_f16(float* c, uint32_t a0, uint32_t a1, uint32_t a2, uint32_t a3,
                                        uint32_t b0, uint32_t b1) {
    asm volatile(
        "mma.sync.aligned.m16n8k16.row.col.f32.f16.f16.f32 "
        "{%0,%1,%2,%3}, {%4,%5,%6,%7}, {%8,%9}, {%0,%1,%2,%3};"
        : "+f"(c[0]), "+f"(c[1]), "+f"(c[2]), "+f"(c[3])
        : "r"(a0), "r"(a1), "r"(a2), "r"(a3), "r"(b0), "r"(b1));
}
__device__ __forceinline__ void cp16(uint32_t saddr, const void* gptr) {
    asm volatile("cp.async.cg.shared.global [%0], [%1], 16;" :: "r"(saddr), "l"(gptr));
}
#define CP_COMMIT() asm volatile("cp.async.commit_group;" ::: "memory")
#define CP_WAIT(n)  asm volatile("cp.async.wait_group %0;" :: "n"(n) : "memory")
__device__ __forceinline__ float ex2f(float x) { float y; asm("ex2.approx.f32 %0, %1;" : "=f"(y) : "f"(x)); return y; }
__device__ __forceinline__ uint32_t pack_h2(float a, float b) {
    __half2 h = __floats2half2_rn(a, b);
    return *(uint32_t*)&h;
}

// ================= scratch =================
__device__ float g_t1[(size_t)NROWS*D_MODEL];
__device__ float g_h [(size_t)NROWS*D_MODEL];

__device__ __half g_x16 [(size_t)NROWS*D_MODEL];
__device__ __half g_q16 [(size_t)NROWS*D_MODEL];   // pre-scaled by 0.125*log2e
__device__ __half g_k16 [(size_t)NROWS*D_MODEL];
__device__ __half g_v16 [(size_t)NROWS*D_MODEL];
__device__ __half g_c16 [(size_t)NROWS*D_MODEL];
__device__ __half g_h16 [(size_t)NROWS*D_MODEL];
__device__ __half g_f116[(size_t)NROWS*D_FF];
__device__ __half g_wqkv16[(size_t)3*D_MODEL*D_MODEL];
__device__ __half g_wo16 [(size_t)D_MODEL*D_MODEL];
__device__ __half g_w116 [(size_t)D_FF*D_MODEL];
__device__ __half g_w216 [(size_t)D_MODEL*D_FF];

// ================= conversion kernels =================
__global__ __launch_bounds__(256)
void cvt_f16_kernel(const float* __restrict__ in, __half* __restrict__ out, int n)
{
    int i = (blockIdx.x * 256 + threadIdx.x) * 8;
    if (i >= n) return;
    float4 v0 = *(const float4*)(in + i);
    float4 v1 = *(const float4*)(in + i + 4);
    uint4 o;
    o.x = pack_h2(v0.x, v0.y);
    o.y = pack_h2(v0.z, v0.w);
    o.z = pack_h2(v1.x, v1.y);
    o.w = pack_h2(v1.z, v1.w);
    *(uint4*)(out + i) = o;
}

// W [K, M] f32 -> T[rowoff + m, k] fp16
__global__ __launch_bounds__(256)
void transpose_cvt_kernel(const float* __restrict__ W, __half* __restrict__ T,
                          int K, int M, int rowoff)
{
    __shared__ float ts[32][33];
    const int m0 = blockIdx.x * 32, k0 = blockIdx.y * 32;
    const int tx = threadIdx.x, ty = threadIdx.y;   // 32 x 8
    #pragma unroll
    for (int i = 0; i < 4; i++) {
        int k = ty + i*8;
        ts[k][tx] = W[(size_t)(k0+k)*M + m0 + tx];
    }
    __syncthreads();
    #pragma unroll
    for (int i = 0; i < 4; i++) {
        int m = ty + i*8;
        T[(size_t)(rowoff + m0 + m)*K + k0 + tx] = __float2half_rn(ts[tx][m]);
    }
}

// ================= mma.sync fp16 GEMM ======================================
// C[row,col] = sum_k A[row,k]*B[col,k] + bias[col]
// MODE 0: f32 -> Cf.  MODE 1: relu -> fp16 C0.
// MODE 3: fused QKV: sec0 -> C0 (scaled by qscale), sec1 -> C1, sec2 -> C2.
// Smem: 2 buffers x (A 16KB | B 16KB) = 64KB.
#define GEMM_SMEM (2*32768)

template<int MODE>
__global__ __launch_bounds__(256, 2)
void gemm_mma(const __half* __restrict__ A16, const __half* __restrict__ B16,
              const float* __restrict__ bias, const float* __restrict__ bias2,
              const float* __restrict__ bias3,
              float* __restrict__ Cf,
              __half* __restrict__ C0, __half* __restrict__ C1, __half* __restrict__ C2,
              int K, int M)
{
    extern __shared__ char sb[];
    const int tid  = threadIdx.x;
    const int wid  = tid >> 5;
    const int lane = tid & 31;
    const int wm   = wid >> 2;            // 0..1
    const int wn   = wid & 3;             // 0..3
    const int brow = blockIdx.y * 128;
    const int bcol = blockIdx.x * 128;
    const uint32_t sbu = smem_u32(sb);

    float acc[4][4][4];
    #pragma unroll
    for (int mf = 0; mf < 4; mf++)
      #pragma unroll
      for (int nf = 0; nf < 4; nf++)
        #pragma unroll
        for (int q = 0; q < 4; q++) acc[mf][nf][q] = 0.f;

    const int NC = K >> 6;
    const __half* srcs[2] = {A16, B16};
    const int bases[2] = {brow, bcol};

    {   // prefetch chunk 0: 2 tiles x 1024 cp16 = 2048 -> 8/thread
        #pragma unroll
        for (int it = 0; it < 8; it++) {
            int idx  = tid + it*256;
            int tile = idx >> 10;
            int rem  = idx & 1023;
            int r    = rem >> 3;
            int chn  = rem & 7;
            const __half* g = srcs[tile] + (size_t)(bases[tile] + r)*K + chn*8;
            cp16(sbu + (uint32_t)tile*16384u + SWZ128((uint32_t)((r << 7) + (chn << 4))), g);
        }
        CP_COMMIT();
    }

    for (int c = 0; c < NC; c++) {
        if (c + 1 < NC) {
            const int kc = (c+1) << 6;
            const uint32_t boff = (uint32_t)((c+1) & 1) * 32768u;
            #pragma unroll
            for (int it = 0; it < 8; it++) {
                int idx  = tid + it*256;
                int tile = idx >> 10;
                int rem  = idx & 1023;
                int r    = rem >> 3;
                int chn  = rem & 7;
                const __half* g = srcs[tile] + (size_t)(bases[tile] + r)*K + kc + chn*8;
                cp16(sbu + boff + (uint32_t)tile*16384u + SWZ128((uint32_t)((r << 7) + (chn << 4))), g);
            }
            CP_COMMIT();
            CP_WAIT(1);
        } else {
            CP_WAIT(0);
        }
        __syncthreads();

        const uint32_t buf = sbu + (uint32_t)(c & 1) * 32768u;
        const uint32_t aB  = buf;
        const uint32_t bB  = buf + 16384u;

        const int rloc   = (lane & 7) + ((lane >> 3) & 1) * 8;
        const int kpiece = (lane >> 4) << 4;

        #pragma unroll
        for (int ks = 0; ks < 4; ks++) {
            const uint32_t wb = (uint32_t)(ks*32 + kpiece);
            uint32_t af[4][4];
            #pragma unroll
            for (int mf = 0; mf < 4; mf++) {
                uint32_t off = SWZ128((uint32_t)(((wm*64 + mf*16 + rloc) << 7)) + wb);
                ldsm_x4(af[mf][0], af[mf][1], af[mf][2], af[mf][3], aB + off);
            }
            uint32_t bf[2][4];
            #pragma unroll
            for (int g = 0; g < 2; g++) {
                uint32_t off = SWZ128((uint32_t)(((wn*32 + g*16 + rloc) << 7)) + wb);
                ldsm_x4(bf[g][0], bf[g][1], bf[g][2], bf[g][3], bB + off);
            }
            #pragma unroll
            for (int mf = 0; mf < 4; mf++) {
                #pragma unroll
                for (int g = 0; g < 2; g++) {
                    mma_f16(acc[mf][g*2],   af[mf][0], af[mf][1], af[mf][2], af[mf][3], bf[g][0], bf[g][2]);
                    mma_f16(acc[mf][g*2+1], af[mf][0], af[mf][1], af[mf][2], af[mf][3], bf[g][1], bf[g][3]);
                }
            }
        }
        __syncthreads();
    }

    const int qr = lane >> 2;
    const int qc = (lane & 3) * 2;

    int sec = 0;
    const float* bi = bias;
    __half* Dh = C0;
    int ostride = M;
    float oscale = 1.f;
    if (MODE == 3) {
        sec = bcol >> 10;
        bi  = (sec == 0) ? bias : (sec == 1 ? bias2 : bias3);
        Dh  = (sec == 0) ? C0 : (sec == 1 ? C1 : C2);
        ostride = D_MODEL;
        if (sec == 0) oscale = 0.125f * 1.44269504f;   // fold attention scale into Q
    }

    #pragma unroll
    for (int mf = 0; mf < 4; mf++) {
        #pragma unroll
        for (int nf = 0; nf < 4; nf++) {
            const int row  = brow + wm*64 + mf*16 + qr;
            const int col  = bcol + wn*32 + nf*8 + qc;
            const int colS = (MODE == 3) ? (col & 1023) : col;
            const float b0 = __ldg(bi + colS), b1 = __ldg(bi + colS + 1);
            float v00 = acc[mf][nf][0] + b0, v01 = acc[mf][nf][1] + b1;
            float v10 = acc[mf][nf][2] + b0, v11 = acc[mf][nf][3] + b1;
            if (MODE == 0) {
                *(float2*)(Cf + (size_t)row*M + colS)     = make_float2(v00, v01);
                *(float2*)(Cf + (size_t)(row+8)*M + colS) = make_float2(v10, v11);
            } else {
                if (MODE == 1) {
                    v00 = fmaxf(v00, 0.f); v01 = fmaxf(v01, 0.f);
                    v10 = fmaxf(v10, 0.f); v11 = fmaxf(v11, 0.f);
                }
                if (MODE == 3) {
                    v00 *= oscale; v01 *= oscale; v10 *= oscale; v11 *= oscale;
                }
                *(uint32_t*)(Dh + (size_t)row*ostride + colS)     = pack_h2(v00, v01);
                *(uint32_t*)(Dh + (size_t)(row+8)*ostride + colS) = pack_h2(v10, v11);
            }
        }
    }
}

// ================= mma.sync fp16 flash attention ===========================
// BQ=128, BK=64, dk=64. 8 warps; warp w owns rows w*16..w*16+15.
// Smem: Q 16KB + 2 x (K 8KB | V 8KB) = 48KB.
#define ATT_SMEM (16384 + 2*16384)

__global__ __launch_bounds__(256)
void attention_mma(const __half* __restrict__ Q16,
                   const __half* __restrict__ K16, const __half* __restrict__ V16,
                   __half* __restrict__ ctx16)
{
    extern __shared__ char sb[];
    const uint32_t sbu = smem_u32(sb);
    const int tid  = threadIdx.x;
    const int wid  = tid >> 5;
    const int lane = tid & 31;
    const int bh   = blockIdx.y;
    const int b    = bh >> 4;
    const int hh   = bh & 15;
    const int q0   = blockIdx.x * 128;
    const size_t rbase = (size_t)b*SEQ*D_MODEL + (size_t)hh*DKH;

    // ---- async-load Q tile (prescaled fp16): 128x64 = 16KB = 1024 cp16 ----
    {
        #pragma unroll
        for (int it = 0; it < 4; it++) {
            int idx = tid + it*256;           // 0..1023
            int r   = idx >> 3;
            int chn = idx & 7;
            const __half* g = Q16 + rbase + (size_t)(q0 + r)*D_MODEL + chn*8;
            cp16(sbu + SWZ128((uint32_t)((r << 7) + (chn << 4))), g);
        }
        CP_COMMIT();
    }
    // ---- prefetch KV tile 0 ----
    const __half* kvsrc[2] = {K16, V16};
    {
        #pragma unroll
        for (int it = 0; it < 4; it++) {
            int idx  = tid + it*256;          // 0..1023
            int tile = idx >> 9;
            int rem  = idx & 511;
            int r    = rem >> 3;
            int chn  = rem & 7;
            const __half* g = kvsrc[tile] + rbase + (size_t)r*D_MODEL + chn*8;
            cp16(sbu + 16384u + (uint32_t)tile*8192u + SWZ128((uint32_t)((r << 7) + (chn << 4))), g);
        }
        CP_COMMIT();
    }

    const int rloc   = (lane & 7) + ((lane >> 3) & 1) * 8;
    const int kpiece = (lane >> 4) << 4;

    // Q fragments (Q was the first commit group; wait until only 1 newer group pending)
    CP_WAIT(1);
    __syncthreads();
    uint32_t qf[4][4];
    #pragma unroll
    for (int ks = 0; ks < 4; ks++) {
        uint32_t off = SWZ128((uint32_t)(((wid*16 + rloc) << 7) + ks*32 + kpiece));
        ldsm_x4(qf[ks][0], qf[ks][1], qf[ks][2], qf[ks][3], sbu + off);
    }

    float O[8][4];
    #pragma unroll
    for (int nt = 0; nt < 8; nt++)
      #pragma unroll
      for (int q = 0; q < 4; q++) O[nt][q] = 0.f;
    float m0 = -1e30f, m1 = -1e30f, l0 = 0.f, l1 = 0.f;

    const int NT = SEQ / 64;
    for (int t = 0; t < NT; t++) {
        if (t + 1 < NT) {
            const int s0 = (t+1) * 64;
            const uint32_t boff = 16384u + (uint32_t)((t+1) & 1) * 16384u;
            #pragma unroll
            for (int it = 0; it < 4; it++) {
                int idx  = tid + it*256;
                int tile = idx >> 9;
                int rem  = idx & 511;
                int r    = rem >> 3;
                int chn  = rem & 7;
                const __half* g = kvsrc[tile] + rbase + (size_t)(s0+r)*D_MODEL + chn*8;
                cp16(sbu + boff + (uint32_t)tile*8192u + SWZ128((uint32_t)((r << 7) + (chn << 4))), g);
            }
            CP_COMMIT();
            CP_WAIT(1);
        } else {
            CP_WAIT(0);
        }
        __syncthreads();

        const uint32_t kb = sbu + 16384u + (uint32_t)(t & 1) * 16384u;
        const uint32_t vb = kb + 8192u;

        // ---- S = Q K^T (log2-domain, Q prescaled) ----
        float sc[8][4];
        #pragma unroll
        for (int nt = 0; nt < 8; nt++)
          #pragma unroll
          for (int q = 0; q < 4; q++) sc[nt][q] = 0.f;

        #pragma unroll
        for (int ks = 0; ks < 4; ks++) {
            #pragma unroll
            for (int g = 0; g < 4; g++) {
                uint32_t kf[4];
                uint32_t off = SWZ128((uint32_t)(((g*16 + rloc) << 7) + ks*32 + kpiece));
                ldsm_x4(kf[0], kf[1], kf[2], kf[3], kb + off);
                mma_f16(sc[g*2],   qf[ks][0], qf[ks][1], qf[ks][2], qf[ks][3], kf[0], kf[2]);
                mma_f16(sc[g*2+1], qf[ks][0], qf[ks][1], qf[ks][2], qf[ks][3], kf[1], kf[3]);
            }
        }

        // ---- online softmax (base-2), quad shuffles ----
        float mx0 = -1e30f, mx1 = -1e30f;
        #pragma unroll
        for (int nt = 0; nt < 8; nt++) {
            mx0 = fmaxf(mx0, fmaxf(sc[nt][0], sc[nt][1]));
            mx1 = fmaxf(mx1, fmaxf(sc[nt][2], sc[nt][3]));
        }
        mx0 = fmaxf(mx0, __shfl_xor_sync(0xffffffffu, mx0, 1));
        mx0 = fmaxf(mx0, __shfl_xor_sync(0xffffffffu, mx0, 2));
        mx1 = fmaxf(mx1, __shfl_xor_sync(0xffffffffu, mx1, 1));
        mx1 = fmaxf(mx1, __shfl_xor_sync(0xffffffffu, mx1, 2));
        const float mn0 = fmaxf(m0, mx0), mn1 = fmaxf(m1, mx1);
        const float a0 = ex2f(m0 - mn0), a1 = ex2f(m1 - mn1);
        float s0 = 0.f, s1 = 0.f;
        #pragma unroll
        for (int nt = 0; nt < 8; nt++) {
            sc[nt][0] = ex2f(sc[nt][0] - mn0);
            sc[nt][1] = ex2f(sc[nt][1] - mn0);
            sc[nt][2] = ex2f(sc[nt][2] - mn1);
            sc[nt][3] = ex2f(sc[nt][3] - mn1);
            s0 += sc[nt][0] + sc[nt][1];
            s1 += sc[nt][2] + sc[nt][3];
        }
        s0 += __shfl_xor_sync(0xffffffffu, s0, 1);
        s0 += __shfl_xor_sync(0xffffffffu, s0, 2);
        s1 += __shfl_xor_sync(0xffffffffu, s1, 1);
        s1 += __shfl_xor_sync(0xffffffffu, s1, 2);
        l0 = l0*a0 + s0; l1 = l1*a1 + s1;
        m0 = mn0; m1 = mn1;
        #pragma unroll
        for (int nt = 0; nt < 8; nt++) {
            O[nt][0] *= a0; O[nt][1] *= a0;
            O[nt][2] *= a1; O[nt][3] *= a1;
        }

        // ---- O += P V ----
        #pragma unroll
        for (int ks = 0; ks < 4; ks++) {
            const int e = 2*ks, o = 2*ks + 1;
            uint32_t p0 = pack_h2(sc[e][0], sc[e][1]);
            uint32_t p1 = pack_h2(sc[e][2], sc[e][3]);
            uint32_t p2 = pack_h2(sc[o][0], sc[o][1]);
            uint32_t p3 = pack_h2(sc[o][2], sc[o][3]);
            #pragma unroll
            for (int dg = 0; dg < 4; dg++) {
                uint32_t vf[4];
                uint32_t off = SWZ128((uint32_t)(((ks*16 + rloc) << 7) + dg*32 + kpiece));
                ldsm_x4_t(vf[0], vf[1], vf[2], vf[3], vb + off);
                mma_f16(O[dg*2],   p0, p1, p2, p3, vf[0], vf[1]);
                mma_f16(O[dg*2+1], p0, p1, p2, p3, vf[2], vf[3]);
            }
        }
        __syncthreads();
    }

    // ---- epilogue: normalize, fp16 write ----
    const float i0 = 1.f / l0, i1 = 1.f / l1;
    const int qr = lane >> 2;
    const int qc = (lane & 3) * 2;
    const int rowA = q0 + wid*16 + qr;
    #pragma unroll
    for (int nt = 0; nt < 8; nt++) {
        float v0 = O[nt][0]*i0, v1 = O[nt][1]*i0;
        float v2 = O[nt][2]*i1, v3 = O[nt][3]*i1;
        size_t oA = rbase + (size_t)rowA*D_MODEL + nt*8 + qc;
        size_t oB = oA + 8*D_MODEL;
        *(uint32_t*)(ctx16 + oA) = pack_h2(v0, v1);
        *(uint32_t*)(ctx16 + oB) = pack_h2(v2, v3);
    }
}

// ================= residual add + LayerNorm ================================
template<bool EMIT16>
__global__ __launch_bounds__(256)
void add_ln_kernel(const float* __restrict__ A, const float* __restrict__ Bm,
                   const float* __restrict__ gamma, const float* __restrict__ beta,
                   float* __restrict__ out, __half* __restrict__ o16)
{
    __shared__ float sh[8];
    const int row = blockIdx.x;
    const int tid = threadIdx.x;
    const float* a  = A  + (size_t)row*D_MODEL;
    const float* bb = Bm + (size_t)row*D_MODEL;
    float v[4];
    float s = 0.f;
    #pragma unroll
    for (int i = 0; i < 4; i++) { int c = tid + i*256; v[i] = a[c] + bb[c]; s += v[i]; }
    #pragma unroll
    for (int o = 16; o; o >>= 1) s += __shfl_xor_sync(0xffffffffu, s, o);
    if ((tid & 31) == 0) sh[tid >> 5] = s;
    __syncthreads();
    float tot = 0.f;
    #pragma unroll
    for (int i = 0; i < 8; i++) tot += sh[i];
    const float mean = tot * (1.f/(float)D_MODEL);
    float s2 = 0.f;
    #pragma unroll
    for (int i = 0; i < 4; i++) { float d = v[i]-mean; s2 += d*d; }
    #pragma unroll
    for (int o = 16; o; o >>= 1) s2 += __shfl_xor_sync(0xffffffffu, s2, o);
    __syncthreads();
    if ((tid & 31) == 0) sh[tid >> 5] = s2;
    __syncthreads();
    float tot2 = 0.f;
    #pragma unroll
    for (int i = 0; i < 8; i++) tot2 += sh[i];
    const float inv = 1.f / (sqrtf(tot2 * (1.f/(float)D_MODEL)) + LN_EPS);
    #pragma unroll
    for (int i = 0; i < 4; i++) {
        int c = tid + i*256;
        float r = gamma[c]*(v[i]-mean)*inv + beta[c];
        out[(size_t)row*D_MODEL + c] = r;
        if (EMIT16) o16[(size_t)row*D_MODEL + c] = __float2half_rn(r);
    }
}

// ================= launcher =================
extern "C" void kernel_launch(void* const* d_in, const int* in_sizes, int n_in,
                              void* d_out, int out_size)
{
    const float* x   = (const float*)d_in[0];
    const float* Wq  = (const float*)d_in[1];
    const float* bq  = (const float*)d_in[2];
    const float* Wk  = (const float*)d_in[3];
    const float* bk  = (const float*)d_in[4];
    const float* Wv  = (const float*)d_in[5];
    const float* bv  = (const float*)d_in[6];
    const float* Wo  = (const float*)d_in[7];
    const float* bo  = (const float*)d_in[8];
    const float* W1  = (const float*)d_in[9];
    const float* b1  = (const float*)d_in[10];
    const float* W2  = (const float*)d_in[11];
    const float* b2  = (const float*)d_in[12];
    const float* g1  = (const float*)d_in[13];
    const float* be1 = (const float*)d_in[14];
    const float* g2  = (const float*)d_in[15];
    const float* be2 = (const float*)d_in[16];
    float* out = (float*)d_out;

    float *t1,*h;
    __half *x16,*q16,*k16,*v16,*c16,*h16,*f116,*wqkv16,*wo16,*w116,*w216;
    cudaGetSymbolAddress((void**)&t1,     g_t1);
    cudaGetSymbolAddress((void**)&h,      g_h);
    cudaGetSymbolAddress((void**)&x16,    g_x16);
    cudaGetSymbolAddress((void**)&q16,    g_q16);
    cudaGetSymbolAddress((void**)&k16,    g_k16);
    cudaGetSymbolAddress((void**)&v16,    g_v16);
    cudaGetSymbolAddress((void**)&c16,    g_c16);
    cudaGetSymbolAddress((void**)&h16,    g_h16);
    cudaGetSymbolAddress((void**)&f116,   g_f116);
    cudaGetSymbolAddress((void**)&wqkv16, g_wqkv16);
    cudaGetSymbolAddress((void**)&wo16,   g_wo16);
    cudaGetSymbolAddress((void**)&w116,   g_w116);
    cudaGetSymbolAddress((void**)&w216,   g_w216);

    cudaFuncSetAttribute(gemm_mma<0>, cudaFuncAttributeMaxDynamicSharedMemorySize, GEMM_SMEM);
    cudaFuncSetAttribute(gemm_mma<1>, cudaFuncAttributeMaxDynamicSharedMemorySize, GEMM_SMEM);
    cudaFuncSetAttribute(gemm_mma<3>, cudaFuncAttributeMaxDynamicSharedMemorySize, GEMM_SMEM);
    cudaFuncSetAttribute(attention_mma, cudaFuncAttributeMaxDynamicSharedMemorySize, ATT_SMEM);

    const int nX = NROWS*D_MODEL;
    dim3 tt(32, 8);
    dim3 thr(256);

    cvt_f16_kernel<<<nX/2048, 256>>>(x, x16, nX);
    transpose_cvt_kernel<<<dim3(D_MODEL/32, D_MODEL/32), tt>>>(Wq, wqkv16, D_MODEL, D_MODEL, 0);
    transpose_cvt_kernel<<<dim3(D_MODEL/32, D_MODEL/32), tt>>>(Wk, wqkv16, D_MODEL, D_MODEL, D_MODEL);
    transpose_cvt_kernel<<<dim3(D_MODEL/32, D_MODEL/32), tt>>>(Wv, wqkv16, D_MODEL, D_MODEL, 2*D_MODEL);
    transpose_cvt_kernel<<<dim3(D_MODEL/32, D_MODEL/32), tt>>>(Wo, wo16, D_MODEL, D_MODEL, 0);

    // fused QKV (Q prescaled fp16, K/V fp16)
    gemm_mma<3><<<dim3(24, 32), thr, GEMM_SMEM>>>(x16, wqkv16, bq, bk, bv,
                                                  nullptr, q16, k16, v16, D_MODEL, D_MODEL);
    // attention
    attention_mma<<<dim3(SEQ/128, BATCH*NHEADS), thr, ATT_SMEM>>>(q16, k16, v16, c16);
    // Wo -> t1 (f32)
    gemm_mma<0><<<dim3(8, 32), thr, GEMM_SMEM>>>(c16, wo16, bo, nullptr, nullptr,
                                                 t1, nullptr, nullptr, nullptr, D_MODEL, D_MODEL);
    // LN1 -> h (f32) + h16
    add_ln_kernel<true><<<NROWS, thr>>>(x, t1, g1, be1, h, h16);
    // FFN weight transposes (deferred)
    transpose_cvt_kernel<<<dim3(D_FF/32,    D_MODEL/32), tt>>>(W1, w116, D_MODEL, D_FF, 0);
    transpose_cvt_kernel<<<dim3(D_MODEL/32, D_FF/32),    tt>>>(W2, w216, D_FF, D_MODEL, 0);
    // FF1 (relu -> fp16)
    gemm_mma<1><<<dim3(32, 32), thr, GEMM_SMEM>>>(h16, w116, b1, nullptr, nullptr,
                                                  nullptr, f116, nullptr, nullptr, D_MODEL, D_FF);
    // FF2 -> t1 (f32)
    gemm_mma<0><<<dim3(8, 32), thr, GEMM_SMEM>>>(f116, w216, b2, nullptr, nullptr,
                                                 t1, nullptr, nullptr, nullptr, D_FF, D_MODEL);
    // LN2 -> out
    add_ln_kernel<false><<<NROWS, thr>>>(h, t1, g2, be2, out, nullptr);
}

// round 9
// speedup vs baseline: 6.6002x; 1.0357x over previous
#include <cuda_runtime.h>
#include <cuda_fp16.h>
#include <math.h>
#include <stdint.h>

#define D_MODEL 1024
#define NHEADS  16
#define DKH     64
#define D_FF    4096
#define BATCH   2
#define SEQ     2048
#define NROWS   (BATCH*SEQ)
#define LN_EPS  1e-6f

#define SWZ128(x) ((x) ^ (((x) >> 3) & 0x70))

// ================= PTX helpers ============================================
__device__ __forceinline__ uint32_t smem_u32(const void* p) {
    uint32_t a;
    asm("{ .reg .u64 t; cvta.to.shared.u64 t, %1; cvt.u32.u64 %0, t; }" : "=r"(a) : "l"(p));
    return a;
}
__device__ __forceinline__ void ldsm_x4(uint32_t& r0, uint32_t& r1, uint32_t& r2, uint32_t& r3, uint32_t addr) {
    asm volatile("ldmatrix.sync.aligned.m8n8.x4.shared.b16 {%0,%1,%2,%3}, [%4];"
                 : "=r"(r0), "=r"(r1), "=r"(r2), "=r"(r3) : "r"(addr));
}
__device__ __forceinline__ void ldsm_x4_t(uint32_t& r0, uint32_t& r1, uint32_t& r2, uint32_t& r3, uint32_t addr) {
    asm volatile("ldmatrix.sync.aligned.m8n8.x4.trans.shared.b16 {%0,%1,%2,%3}, [%4];"
                 : "=r"(r0), "=r"(r1), "=r"(r2), "=r"(r3) : "r"(addr));
}
__device__ __forceinline__ void mma_f16(float* c, uint32_t a0, uint32_t a1, uint32_t a2, uint32_t a3,
                                        uint32_t b0, uint32_t b1) {
    asm volatile(
        "mma.sync.aligned.m16n8k16.row.col.f32.f16.f16.f32 "
        "{%0,%1,%2,%3}, {%4,%5,%6,%7}, {%8,%9}, {%0,%1,%2,%3};"
        : "+f"(c[0]), "+f"(c[1]), "+f"(c[2]), "+f"(c[3])
        : "r"(a0), "r"(a1), "r"(a2), "r"(a3), "r"(b0), "r"(b1));
}
__device__ __forceinline__ void cp16(uint32_t saddr, const void* gptr) {
    asm volatile("cp.async.cg.shared.global [%0], [%1], 16;" :: "r"(saddr), "l"(gptr));
}
#define CP_COMMIT() asm volatile("cp.async.commit_group;" ::: "memory")
#define CP_WAIT(n)  asm volatile("cp.async.wait_group %0;" :: "n"(n) : "memory")
__device__ __forceinline__ float ex2f(float x) { float y; asm("ex2.approx.f32 %0, %1;" : "=f"(y) : "f"(x)); return y; }
__device__ __forceinline__ uint32_t h2ex2(uint32_t x) {
    uint32_t y; asm("ex2.approx.f16x2 %0, %1;" : "=r"(y) : "r"(x)); return y;
}
__device__ __forceinline__ uint32_t pack_h2(float a, float b) {
    __half2 h = __floats2half2_rn(a, b);
    return *(uint32_t*)&h;
}

// ================= scratch =================
__device__ float g_t1[(size_t)NROWS*D_MODEL];
__device__ float g_h [(size_t)NROWS*D_MODEL];

__device__ __half g_x16 [(size_t)NROWS*D_MODEL];
__device__ __half g_q16 [(size_t)NROWS*D_MODEL];   // pre-scaled by 0.125*log2e
__device__ __half g_k16 [(size_t)NROWS*D_MODEL];
__device__ __half g_v16 [(size_t)NROWS*D_MODEL];
__device__ __half g_c16 [(size_t)NROWS*D_MODEL];
__device__ __half g_h16 [(size_t)NROWS*D_MODEL];
__device__ __half g_f116[(size_t)NROWS*D_FF];
__device__ __half g_wqkv16[(size_t)3*D_MODEL*D_MODEL];
__device__ __half g_wo16 [(size_t)D_MODEL*D_MODEL];
__device__ __half g_w116 [(size_t)D_FF*D_MODEL];
__device__ __half g_w216 [(size_t)D_MODEL*D_FF];

// ================= conversion kernels =================
__global__ __launch_bounds__(256)
void cvt_f16_kernel(const float* __restrict__ in, __half* __restrict__ out, int n)
{
    int i = (blockIdx.x * 256 + threadIdx.x) * 8;
    if (i >= n) return;
    float4 v0 = *(const float4*)(in + i);
    float4 v1 = *(const float4*)(in + i + 4);
    uint4 o;
    o.x = pack_h2(v0.x, v0.y);
    o.y = pack_h2(v0.z, v0.w);
    o.z = pack_h2(v1.x, v1.y);
    o.w = pack_h2(v1.z, v1.w);
    *(uint4*)(out + i) = o;
}

// ALL weight transposes in one launch. 12288 blocks:
//   [0,1024)    Wq -> wqkv rowoff 0      (K=1024, M=1024)
//   [1024,2048) Wk -> wqkv rowoff 1024
//   [2048,3072) Wv -> wqkv rowoff 2048
//   [3072,4096) Wo -> wo
//   [4096,8192) W1 -> w1 (K=1024, M=4096)
//   [8192,12288) W2 -> w2 (K=4096, M=1024)
__global__ __launch_bounds__(256)
void transpose_all_kernel(const float* __restrict__ Wq, const float* __restrict__ Wk,
                          const float* __restrict__ Wv, const float* __restrict__ Wo,
                          const float* __restrict__ W1, const float* __restrict__ W2,
                          __half* __restrict__ wqkv, __half* __restrict__ wo,
                          __half* __restrict__ w1,   __half* __restrict__ w2)
{
    __shared__ float ts[32][33];
    const int id = blockIdx.x;
    const float* W; __half* T;
    int K, M, rowoff, bx, by;
    if (id < 4096) {
        int mat = id >> 10, r = id & 1023;
        bx = r & 31; by = r >> 5;
        K = 1024; M = 1024;
        if      (mat == 0) { W = Wq; T = wqkv; rowoff = 0;    }
        else if (mat == 1) { W = Wk; T = wqkv; rowoff = 1024; }
        else if (mat == 2) { W = Wv; T = wqkv; rowoff = 2048; }
        else               { W = Wo; T = wo;   rowoff = 0;    }
    } else if (id < 8192) {
        int r = id - 4096;
        bx = r & 127; by = r >> 7;
        K = 1024; M = 4096; W = W1; T = w1; rowoff = 0;
    } else {
        int r = id - 8192;
        bx = r & 31; by = r >> 5;
        K = 4096; M = 1024; W = W2; T = w2; rowoff = 0;
    }
    const int m0 = bx * 32, k0 = by * 32;
    const int tx = threadIdx.x, ty = threadIdx.y;   // 32 x 8
    #pragma unroll
    for (int i = 0; i < 4; i++) {
        int k = ty + i*8;
        ts[k][tx] = W[(size_t)(k0+k)*M + m0 + tx];
    }
    __syncthreads();
    #pragma unroll
    for (int i = 0; i < 4; i++) {
        int m = ty + i*8;
        T[(size_t)(rowoff + m0 + m)*K + k0 + tx] = __float2half_rn(ts[tx][m]);
    }
}

// ================= mma.sync fp16 GEMM ======================================
// MODE 0: f32 -> Cf.  MODE 1: relu -> fp16 C0.
// MODE 3: fused QKV: sec0 -> C0 (scaled by qscale), sec1 -> C1, sec2 -> C2.
#define GEMM_SMEM (2*32768)

template<int MODE>
__global__ __launch_bounds__(256, 2)
void gemm_mma(const __half* __restrict__ A16, const __half* __restrict__ B16,
              const float* __restrict__ bias, const float* __restrict__ bias2,
              const float* __restrict__ bias3,
              float* __restrict__ Cf,
              __half* __restrict__ C0, __half* __restrict__ C1, __half* __restrict__ C2,
              int K, int M)
{
    extern __shared__ char sb[];
    const int tid  = threadIdx.x;
    const int wid  = tid >> 5;
    const int lane = tid & 31;
    const int wm   = wid >> 2;
    const int wn   = wid & 3;
    const int brow = blockIdx.y * 128;
    const int bcol = blockIdx.x * 128;
    const uint32_t sbu = smem_u32(sb);

    float acc[4][4][4];
    #pragma unroll
    for (int mf = 0; mf < 4; mf++)
      #pragma unroll
      for (int nf = 0; nf < 4; nf++)
        #pragma unroll
        for (int q = 0; q < 4; q++) acc[mf][nf][q] = 0.f;

    const int NC = K >> 6;
    const __half* srcs[2] = {A16, B16};
    const int bases[2] = {brow, bcol};

    {
        #pragma unroll
        for (int it = 0; it < 8; it++) {
            int idx  = tid + it*256;
            int tile = idx >> 10;
            int rem  = idx & 1023;
            int r    = rem >> 3;
            int chn  = rem & 7;
            const __half* g = srcs[tile] + (size_t)(bases[tile] + r)*K + chn*8;
            cp16(sbu + (uint32_t)tile*16384u + SWZ128((uint32_t)((r << 7) + (chn << 4))), g);
        }
        CP_COMMIT();
    }

    for (int c = 0; c < NC; c++) {
        if (c + 1 < NC) {
            const int kc = (c+1) << 6;
            const uint32_t boff = (uint32_t)((c+1) & 1) * 32768u;
            #pragma unroll
            for (int it = 0; it < 8; it++) {
                int idx  = tid + it*256;
                int tile = idx >> 10;
                int rem  = idx & 1023;
                int r    = rem >> 3;
                int chn  = rem & 7;
                const __half* g = srcs[tile] + (size_t)(bases[tile] + r)*K + kc + chn*8;
                cp16(sbu + boff + (uint32_t)tile*16384u + SWZ128((uint32_t)((r << 7) + (chn << 4))), g);
            }
            CP_COMMIT();
            CP_WAIT(1);
        } else {
            CP_WAIT(0);
        }
        __syncthreads();

        const uint32_t buf = sbu + (uint32_t)(c & 1) * 32768u;
        const uint32_t aB  = buf;
        const uint32_t bB  = buf + 16384u;

        const int rloc   = (lane & 7) + ((lane >> 3) & 1) * 8;
        const int kpiece = (lane >> 4) << 4;

        #pragma unroll
        for (int ks = 0; ks < 4; ks++) {
            const uint32_t wb = (uint32_t)(ks*32 + kpiece);
            uint32_t af[4][4];
            #pragma unroll
            for (int mf = 0; mf < 4; mf++) {
                uint32_t off = SWZ128((uint32_t)(((wm*64 + mf*16 + rloc) << 7)) + wb);
                ldsm_x4(af[mf][0], af[mf][1], af[mf][2], af[mf][3], aB + off);
            }
            uint32_t bf[2][4];
            #pragma unroll
            for (int g = 0; g < 2; g++) {
                uint32_t off = SWZ128((uint32_t)(((wn*32 + g*16 + rloc) << 7)) + wb);
                ldsm_x4(bf[g][0], bf[g][1], bf[g][2], bf[g][3], bB + off);
            }
            #pragma unroll
            for (int mf = 0; mf < 4; mf++) {
                #pragma unroll
                for (int g = 0; g < 2; g++) {
                    mma_f16(acc[mf][g*2],   af[mf][0], af[mf][1], af[mf][2], af[mf][3], bf[g][0], bf[g][2]);
                    mma_f16(acc[mf][g*2+1], af[mf][0], af[mf][1], af[mf][2], af[mf][3], bf[g][1], bf[g][3]);
                }
            }
        }
        __syncthreads();
    }

    const int qr = lane >> 2;
    const int qc = (lane & 3) * 2;

    int sec = 0;
    const float* bi = bias;
    __half* Dh = C0;
    int ostride = M;
    float oscale = 1.f;
    if (MODE == 3) {
        sec = bcol >> 10;
        bi  = (sec == 0) ? bias : (sec == 1 ? bias2 : bias3);
        Dh  = (sec == 0) ? C0 : (sec == 1 ? C1 : C2);
        ostride = D_MODEL;
        if (sec == 0) oscale = 0.125f * 1.44269504f;
    }

    #pragma unroll
    for (int mf = 0; mf < 4; mf++) {
        #pragma unroll
        for (int nf = 0; nf < 4; nf++) {
            const int row  = brow + wm*64 + mf*16 + qr;
            const int col  = bcol + wn*32 + nf*8 + qc;
            const int colS = (MODE == 3) ? (col & 1023) : col;
            const float b0 = __ldg(bi + colS), b1 = __ldg(bi + colS + 1);
            float v00 = acc[mf][nf][0] + b0, v01 = acc[mf][nf][1] + b1;
            float v10 = acc[mf][nf][2] + b0, v11 = acc[mf][nf][3] + b1;
            if (MODE == 0) {
                *(float2*)(Cf + (size_t)row*M + colS)     = make_float2(v00, v01);
                *(float2*)(Cf + (size_t)(row+8)*M + colS) = make_float2(v10, v11);
            } else {
                if (MODE == 1) {
                    v00 = fmaxf(v00, 0.f); v01 = fmaxf(v01, 0.f);
                    v10 = fmaxf(v10, 0.f); v11 = fmaxf(v11, 0.f);
                }
                if (MODE == 3) {
                    v00 *= oscale; v01 *= oscale; v10 *= oscale; v11 *= oscale;
                }
                *(uint32_t*)(Dh + (size_t)row*ostride + colS)     = pack_h2(v00, v01);
                *(uint32_t*)(Dh + (size_t)(row+8)*ostride + colS) = pack_h2(v10, v11);
            }
        }
    }
}

// ================= mma.sync fp16 flash attention ===========================
// BQ=128, BK=64, dk=64. 8 warps; warp w owns rows w*16..w*16+15.
// Softmax: base-2, exp via ex2.approx.f16x2; row sums via ones-MMA.
#define ATT_SMEM (16384 + 2*16384)
#define ONES_H2 0x3C003C00u

__global__ __launch_bounds__(256, 2)
void attention_mma(const __half* __restrict__ Q16,
                   const __half* __restrict__ K16, const __half* __restrict__ V16,
                   __half* __restrict__ ctx16)
{
    extern __shared__ char sb[];
    const uint32_t sbu = smem_u32(sb);
    const int tid  = threadIdx.x;
    const int wid  = tid >> 5;
    const int lane = tid & 31;
    const int bh   = blockIdx.y;
    const int b    = bh >> 4;
    const int hh   = bh & 15;
    const int q0   = blockIdx.x * 128;
    const size_t rbase = (size_t)b*SEQ*D_MODEL + (size_t)hh*DKH;

    // ---- async-load Q tile (prescaled fp16) ----
    {
        #pragma unroll
        for (int it = 0; it < 4; it++) {
            int idx = tid + it*256;
            int r   = idx >> 3;
            int chn = idx & 7;
            const __half* g = Q16 + rbase + (size_t)(q0 + r)*D_MODEL + chn*8;
            cp16(sbu + SWZ128((uint32_t)((r << 7) + (chn << 4))), g);
        }
        CP_COMMIT();
    }
    const __half* kvsrc[2] = {K16, V16};
    {
        #pragma unroll
        for (int it = 0; it < 4; it++) {
            int idx  = tid + it*256;
            int tile = idx >> 9;
            int rem  = idx & 511;
            int r    = rem >> 3;
            int chn  = rem & 7;
            const __half* g = kvsrc[tile] + rbase + (size_t)r*D_MODEL + chn*8;
            cp16(sbu + 16384u + (uint32_t)tile*8192u + SWZ128((uint32_t)((r << 7) + (chn << 4))), g);
        }
        CP_COMMIT();
    }

    const int rloc   = (lane & 7) + ((lane >> 3) & 1) * 8;
    const int kpiece = (lane >> 4) << 4;

    CP_WAIT(1);
    __syncthreads();
    uint32_t qf[4][4];
    #pragma unroll
    for (int ks = 0; ks < 4; ks++) {
        uint32_t off = SWZ128((uint32_t)(((wid*16 + rloc) << 7) + ks*32 + kpiece));
        ldsm_x4(qf[ks][0], qf[ks][1], qf[ks][2], qf[ks][3], sbu + off);
    }

    float O[8][4];
    #pragma unroll
    for (int nt = 0; nt < 8; nt++)
      #pragma unroll
      for (int q = 0; q < 4; q++) O[nt][q] = 0.f;
    float m0 = -1e30f, m1 = -1e30f, l0 = 0.f, l1 = 0.f;

    const int NT = SEQ / 64;
    for (int t = 0; t < NT; t++) {
        if (t + 1 < NT) {
            const int s0 = (t+1) * 64;
            const uint32_t boff = 16384u + (uint32_t)((t+1) & 1) * 16384u;
            #pragma unroll
            for (int it = 0; it < 4; it++) {
                int idx  = tid + it*256;
                int tile = idx >> 9;
                int rem  = idx & 511;
                int r    = rem >> 3;
                int chn  = rem & 7;
                const __half* g = kvsrc[tile] + rbase + (size_t)(s0+r)*D_MODEL + chn*8;
                cp16(sbu + boff + (uint32_t)tile*8192u + SWZ128((uint32_t)((r << 7) + (chn << 4))), g);
            }
            CP_COMMIT();
            CP_WAIT(1);
        } else {
            CP_WAIT(0);
        }
        __syncthreads();

        const uint32_t kb = sbu + 16384u + (uint32_t)(t & 1) * 16384u;
        const uint32_t vb = kb + 8192u;

        // ---- S = Q K^T (log2-domain, Q prescaled) ----
        float sc[8][4];
        #pragma unroll
        for (int nt = 0; nt < 8; nt++)
          #pragma unroll
          for (int q = 0; q < 4; q++) sc[nt][q] = 0.f;

        #pragma unroll
        for (int ks = 0; ks < 4; ks++) {
            #pragma unroll
            for (int g = 0; g < 4; g++) {
                uint32_t kf[4];
                uint32_t off = SWZ128((uint32_t)(((g*16 + rloc) << 7) + ks*32 + kpiece));
                ldsm_x4(kf[0], kf[1], kf[2], kf[3], kb + off);
                mma_f16(sc[g*2],   qf[ks][0], qf[ks][1], qf[ks][2], qf[ks][3], kf[0], kf[2]);
                mma_f16(sc[g*2+1], qf[ks][0], qf[ks][1], qf[ks][2], qf[ks][3], kf[1], kf[3]);
            }
        }

        // ---- online softmax: max in f32, exp in f16x2 ----
        float mx0 = -1e30f, mx1 = -1e30f;
        #pragma unroll
        for (int nt = 0; nt < 8; nt++) {
            mx0 = fmaxf(mx0, fmaxf(sc[nt][0], sc[nt][1]));
            mx1 = fmaxf(mx1, fmaxf(sc[nt][2], sc[nt][3]));
        }
        mx0 = fmaxf(mx0, __shfl_xor_sync(0xffffffffu, mx0, 1));
        mx0 = fmaxf(mx0, __shfl_xor_sync(0xffffffffu, mx0, 2));
        mx1 = fmaxf(mx1, __shfl_xor_sync(0xffffffffu, mx1, 1));
        mx1 = fmaxf(mx1, __shfl_xor_sync(0xffffffffu, mx1, 2));
        const float mn0 = fmaxf(m0, mx0), mn1 = fmaxf(m1, mx1);
        const float a0 = ex2f(m0 - mn0), a1 = ex2f(m1 - mn1);

        // P = 2^(sc - mn) as packed half2: pl[nt] = rows qr, ph[nt] = rows qr+8
        uint32_t pl[8], ph[8];
        #pragma unroll
        for (int nt = 0; nt < 8; nt++) {
            pl[nt] = h2ex2(pack_h2(sc[nt][0] - mn0, sc[nt][1] - mn0));
            ph[nt] = h2ex2(pack_h2(sc[nt][2] - mn1, sc[nt][3] - mn1));
        }

        // row sums of quantized P via tensor core (B = ones)
        float sacc[4] = {0.f, 0.f, 0.f, 0.f};
        #pragma unroll
        for (int ks = 0; ks < 4; ks++)
            mma_f16(sacc, pl[2*ks], ph[2*ks], pl[2*ks+1], ph[2*ks+1], ONES_H2, ONES_H2);

        l0 = l0*a0 + sacc[0];
        l1 = l1*a1 + sacc[2];
        m0 = mn0; m1 = mn1;
        #pragma unroll
        for (int nt = 0; nt < 8; nt++) {
            O[nt][0] *= a0; O[nt][1] *= a0;
            O[nt][2] *= a1; O[nt][3] *= a1;
        }

        // ---- O += P V ----
        #pragma unroll
        for (int ks = 0; ks < 4; ks++) {
            const int e = 2*ks, o = 2*ks + 1;
            #pragma unroll
            for (int dg = 0; dg < 4; dg++) {
                uint32_t vf[4];
                uint32_t off = SWZ128((uint32_t)(((ks*16 + rloc) << 7) + dg*32 + kpiece));
                ldsm_x4_t(vf[0], vf[1], vf[2], vf[3], vb + off);
                mma_f16(O[dg*2],   pl[e], ph[e], pl[o], ph[o], vf[0], vf[1]);
                mma_f16(O[dg*2+1], pl[e], ph[e], pl[o], ph[o], vf[2], vf[3]);
            }
        }
        __syncthreads();
    }

    // ---- epilogue ----
    const float i0 = 1.f / l0, i1 = 1.f / l1;
    const int qr = lane >> 2;
    const int qc = (lane & 3) * 2;
    const int rowA = q0 + wid*16 + qr;
    #pragma unroll
    for (int nt = 0; nt < 8; nt++) {
        float v0 = O[nt][0]*i0, v1 = O[nt][1]*i0;
        float v2 = O[nt][2]*i1, v3 = O[nt][3]*i1;
        size_t oA = rbase + (size_t)rowA*D_MODEL + nt*8 + qc;
        size_t oB = oA + 8*D_MODEL;
        *(uint32_t*)(ctx16 + oA) = pack_h2(v0, v1);
        *(uint32_t*)(ctx16 + oB) = pack_h2(v2, v3);
    }
}

// ================= residual add + LayerNorm ================================
template<bool EMIT16>
__global__ __launch_bounds__(256)
void add_ln_kernel(const float* __restrict__ A, const float* __restrict__ Bm,
                   const float* __restrict__ gamma, const float* __restrict__ beta,
                   float* __restrict__ out, __half* __restrict__ o16)
{
    __shared__ float sh[8];
    const int row = blockIdx.x;
    const int tid = threadIdx.x;
    const float* a  = A  + (size_t)row*D_MODEL;
    const float* bb = Bm + (size_t)row*D_MODEL;
    float v[4];
    float s = 0.f;
    #pragma unroll
    for (int i = 0; i < 4; i++) { int c = tid + i*256; v[i] = a[c] + bb[c]; s += v[i]; }
    #pragma unroll
    for (int o = 16; o; o >>= 1) s += __shfl_xor_sync(0xffffffffu, s, o);
    if ((tid & 31) == 0) sh[tid >> 5] = s;
    __syncthreads();
    float tot = 0.f;
    #pragma unroll
    for (int i = 0; i < 8; i++) tot += sh[i];
    const float mean = tot * (1.f/(float)D_MODEL);
    float s2 = 0.f;
    #pragma unroll
    for (int i = 0; i < 4; i++) { float d = v[i]-mean; s2 += d*d; }
    #pragma unroll
    for (int o = 16; o; o >>= 1) s2 += __shfl_xor_sync(0xffffffffu, s2, o);
    __syncthreads();
    if ((tid & 31) == 0) sh[tid >> 5] = s2;
    __syncthreads();
    float tot2 = 0.f;
    #pragma unroll
    for (int i = 0; i < 8; i++) tot2 += sh[i];
    const float inv = 1.f / (sqrtf(tot2 * (1.f/(float)D_MODEL)) + LN_EPS);
    #pragma unroll
    for (int i = 0; i < 4; i++) {
        int c = tid + i*256;
        float r = gamma[c]*(v[i]-mean)*inv + beta[c];
        out[(size_t)row*D_MODEL + c] = r;
        if (EMIT16) o16[(size_t)row*D_MODEL + c] = __float2half_rn(r);
    }
}

// ================= launcher =================
extern "C" void kernel_launch(void* const* d_in, const int* in_sizes, int n_in,
                              void* d_out, int out_size)
{
    const float* x   = (const float*)d_in[0];
    const float* Wq  = (const float*)d_in[1];
    const float* bq  = (const float*)d_in[2];
    const float* Wk  = (const float*)d_in[3];
    const float* bk  = (const float*)d_in[4];
    const float* Wv  = (const float*)d_in[5];
    const float* bv  = (const float*)d_in[6];
    const float* Wo  = (const float*)d_in[7];
    const float* bo  = (const float*)d_in[8];
    const float* W1  = (const float*)d_in[9];
    const float* b1  = (const float*)d_in[10];
    const float* W2  = (const float*)d_in[11];
    const float* b2  = (const float*)d_in[12];
    const float* g1  = (const float*)d_in[13];
    const float* be1 = (const float*)d_in[14];
    const float* g2  = (const float*)d_in[15];
    const float* be2 = (const float*)d_in[16];
    float* out = (float*)d_out;

    float *t1,*h;
    __half *x16,*q16,*k16,*v16,*c16,*h16,*f116,*wqkv16,*wo16,*w116,*w216;
    cudaGetSymbolAddress((void**)&t1,     g_t1);
    cudaGetSymbolAddress((void**)&h,      g_h);
    cudaGetSymbolAddress((void**)&x16,    g_x16);
    cudaGetSymbolAddress((void**)&q16,    g_q16);
    cudaGetSymbolAddress((void**)&k16,    g_k16);
    cudaGetSymbolAddress((void**)&v16,    g_v16);
    cudaGetSymbolAddress((void**)&c16,    g_c16);
    cudaGetSymbolAddress((void**)&h16,    g_h16);
    cudaGetSymbolAddress((void**)&f116,   g_f116);
    cudaGetSymbolAddress((void**)&wqkv16, g_wqkv16);
    cudaGetSymbolAddress((void**)&wo16,   g_wo16);
    cudaGetSymbolAddress((void**)&w116,   g_w116);
    cudaGetSymbolAddress((void**)&w216,   g_w216);

    cudaFuncSetAttribute(gemm_mma<0>, cudaFuncAttributeMaxDynamicSharedMemorySize, GEMM_SMEM);
    cudaFuncSetAttribute(gemm_mma<1>, cudaFuncAttributeMaxDynamicSharedMemorySize, GEMM_SMEM);
    cudaFuncSetAttribute(gemm_mma<3>, cudaFuncAttributeMaxDynamicSharedMemorySize, GEMM_SMEM);
    cudaFuncSetAttribute(attention_mma, cudaFuncAttributeMaxDynamicSharedMemorySize, ATT_SMEM);

    const int nX = NROWS*D_MODEL;
    dim3 tt(32, 8);
    dim3 thr(256);

    cvt_f16_kernel<<<nX/2048, 256>>>(x, x16, nX);
    transpose_all_kernel<<<12288, tt>>>(Wq, Wk, Wv, Wo, W1, W2,
                                        wqkv16, wo16, w116, w216);
    // fused QKV (Q prescaled fp16, K/V fp16)
    gemm_mma<3><<<dim3(24, 32), thr, GEMM_SMEM>>>(x16, wqkv16, bq, bk, bv,
                                                  nullptr, q16, k16, v16, D_MODEL, D_MODEL);
    // attention
    attention_mma<<<dim3(SEQ/128, BATCH*NHEADS), thr, ATT_SMEM>>>(q16, k16, v16, c16);
    // Wo -> t1 (f32)
    gemm_mma<0><<<dim3(8, 32), thr, GEMM_SMEM>>>(c16, wo16, bo, nullptr, nullptr,
                                                 t1, nullptr, nullptr, nullptr, D_MODEL, D_MODEL);
    // LN1 -> h (f32) + h16
    add_ln_kernel<true><<<NROWS, thr>>>(x, t1, g1, be1, h, h16);
    // FF1 (relu -> fp16)
    gemm_mma<1><<<dim3(32, 32), thr, GEMM_SMEM>>>(h16, w116, b1, nullptr, nullptr,
                                                  nullptr, f116, nullptr, nullptr, D_MODEL, D_FF);
    // FF2 -> t1 (f32)
    gemm_mma<0><<<dim3(8, 32), thr, GEMM_SMEM>>>(f116, w216, b2, nullptr, nullptr,
                                                 t1, nullptr, nullptr, nullptr, D_FF, D_MODEL);
    // LN2 -> out
    add_ln_kernel<false><<<NROWS, thr>>>(h, t1, g2, be2, out, nullptr);
}